// round 4
// baseline (speedup 1.0000x reference)
#include <cuda_runtime.h>
#include <math.h>

#define SEQ 4096
#define DIM 1024

// Scratch (static device memory — no allocation APIs).
__device__ float g_Q[SEQ * DIM];
__device__ float g_K[SEQ * DIM];
__device__ float g_V[SEQ * DIM];
__device__ float g_S[(size_t)SEQ * SEQ];

// ---------------------------------------------------------------------------
// 128x128x16 tiled fp32 GEMM, 8x8 per thread, packed f32x2 FMA inner loop.
//   BT = true : C[M,N] = alpha * A[M,K] * B[N,K]^T (+ bias[N])   (NT)
//   BT = false: C[M,N] = alpha * A[M,K] * B[K,N]   (+ bias[N])   (NN)
// M,N,K multiples of 128/128/16. Grid: (N/128, M/128), 256 threads.
// ---------------------------------------------------------------------------
template <bool BT, bool HAS_BIAS>
__global__ __launch_bounds__(256, 2)
void gemm128(const float* __restrict__ A, const float* __restrict__ B,
             const float* __restrict__ bias, float* __restrict__ C,
             int N, int K, float alpha)
{
    const int bx = blockIdx.x * 128;
    const int by = blockIdx.y * 128;
    const int tid = threadIdx.x;
    const int w = tid >> 5;
    const int l = tid & 31;
    // warp grid 4x2, lane grid 4x8 -> 16x16 threads, each 8x8 outputs
    const int tm = ((w >> 1) << 2) + (l >> 3);   // 0..15 (row group)
    const int tn = ((w & 1) << 3) + (l & 7);     // 0..15 (col group)

    __shared__ float As[16][132];   // +4 pad
    __shared__ float Bs[16][132];

    const int arow = tid >> 2;          // 0..63
    const int acol = (tid & 3) << 2;    // 0,4,8,12

    unsigned long long acc[8][4];       // 8 rows x 4 packed col-pairs
#pragma unroll
    for (int i = 0; i < 8; i++)
#pragma unroll
        for (int j = 0; j < 4; j++) acc[i][j] = 0ull;

    for (int k0 = 0; k0 < K; k0 += 16) {
        // ---- A tile: [128 x 16], stored transposed into As[k][m] ----
        {
            float4 v0 = *(const float4*)(A + (size_t)(by + arow) * K + k0 + acol);
            float4 v1 = *(const float4*)(A + (size_t)(by + arow + 64) * K + k0 + acol);
            As[acol + 0][arow] = v0.x;  As[acol + 1][arow] = v0.y;
            As[acol + 2][arow] = v0.z;  As[acol + 3][arow] = v0.w;
            As[acol + 0][arow + 64] = v1.x;  As[acol + 1][arow + 64] = v1.y;
            As[acol + 2][arow + 64] = v1.z;  As[acol + 3][arow + 64] = v1.w;
        }
        // ---- B tile ----
        if (BT) {
            // B is [N,K]: tile rows are N, transposed into Bs[k][n]
            float4 v0 = *(const float4*)(B + (size_t)(bx + arow) * K + k0 + acol);
            float4 v1 = *(const float4*)(B + (size_t)(bx + arow + 64) * K + k0 + acol);
            Bs[acol + 0][arow] = v0.x;  Bs[acol + 1][arow] = v0.y;
            Bs[acol + 2][arow] = v0.z;  Bs[acol + 3][arow] = v0.w;
            Bs[acol + 0][arow + 64] = v1.x;  Bs[acol + 1][arow + 64] = v1.y;
            Bs[acol + 2][arow + 64] = v1.z;  Bs[acol + 3][arow + 64] = v1.w;
        } else {
            // B is [K,N]: tile rows are K, direct vector store
            const int brow = tid >> 5;          // 0..7
            const int bcol = (tid & 31) << 2;   // 0..124
            float4 v0 = *(const float4*)(B + (size_t)(k0 + brow) * N + bx + bcol);
            float4 v1 = *(const float4*)(B + (size_t)(k0 + brow + 8) * N + bx + bcol);
            *(float4*)&Bs[brow][bcol] = v0;
            *(float4*)&Bs[brow + 8][bcol] = v1;
        }
        __syncthreads();

#pragma unroll
        for (int kk = 0; kk < 16; kk++) {
            float4 alo = *(const float4*)&As[kk][tm * 8];
            float4 ahi = *(const float4*)&As[kk][tm * 8 + 4];
            float4 blo = *(const float4*)&Bs[kk][tn * 8];
            float4 bhi = *(const float4*)&Bs[kk][tn * 8 + 4];
            unsigned long long b2[4];
            asm("mov.b64 %0, {%1, %2};" : "=l"(b2[0]) : "f"(blo.x), "f"(blo.y));
            asm("mov.b64 %0, {%1, %2};" : "=l"(b2[1]) : "f"(blo.z), "f"(blo.w));
            asm("mov.b64 %0, {%1, %2};" : "=l"(b2[2]) : "f"(bhi.x), "f"(bhi.y));
            asm("mov.b64 %0, {%1, %2};" : "=l"(b2[3]) : "f"(bhi.z), "f"(bhi.w));
            float a[8] = {alo.x, alo.y, alo.z, alo.w, ahi.x, ahi.y, ahi.z, ahi.w};
#pragma unroll
            for (int i = 0; i < 8; i++) {
                unsigned long long a2;
                asm("mov.b64 %0, {%1, %1};" : "=l"(a2) : "f"(a[i]));
#pragma unroll
                for (int j = 0; j < 4; j++)
                    asm("fma.rn.f32x2 %0, %1, %2, %0;"
                        : "+l"(acc[i][j]) : "l"(a2), "l"(b2[j]));
            }
        }
        __syncthreads();
    }

    // ---- epilogue ----
    const int crow0 = by + tm * 8;
    const int ccol  = bx + tn * 8;
    float badd[8];
#pragma unroll
    for (int j = 0; j < 8; j++) badd[j] = HAS_BIAS ? bias[ccol + j] : 0.0f;
#pragma unroll
    for (int i = 0; i < 8; i++) {
        float o[8];
#pragma unroll
        for (int j = 0; j < 4; j++) {
            float lo, hi;
            asm("mov.b64 {%0, %1}, %2;" : "=f"(lo), "=f"(hi) : "l"(acc[i][j]));
            o[2 * j]     = lo * alpha + badd[2 * j];
            o[2 * j + 1] = hi * alpha + badd[2 * j + 1];
        }
        float4* cp = (float4*)(C + (size_t)(crow0 + i) * N + ccol);
        cp[0] = make_float4(o[0], o[1], o[2], o[3]);
        cp[1] = make_float4(o[4], o[5], o[6], o[7]);
    }
}

// ---------------------------------------------------------------------------
// Row softmax over 4096-wide rows, in place. One block (256 thr) per row;
// 16 values per thread held in registers across max/exp/sum passes.
// ---------------------------------------------------------------------------
__global__ void softmax4096(float* __restrict__ S)
{
    const int row = blockIdx.x;
    float4* p = (float4*)(S + (size_t)row * SEQ);
    const int t = threadIdx.x;

    float4 v[4];
    float mx = -1e30f;
#pragma unroll
    for (int k = 0; k < 4; k++) {
        v[k] = p[t + 256 * k];
        mx = fmaxf(mx, fmaxf(fmaxf(v[k].x, v[k].y), fmaxf(v[k].z, v[k].w)));
    }
#pragma unroll
    for (int o = 16; o > 0; o >>= 1)
        mx = fmaxf(mx, __shfl_xor_sync(0xffffffffu, mx, o));

    __shared__ float red[8];
    if ((t & 31) == 0) red[t >> 5] = mx;
    __syncthreads();
    mx = red[0];
#pragma unroll
    for (int i = 1; i < 8; i++) mx = fmaxf(mx, red[i]);

    float sum = 0.0f;
#pragma unroll
    for (int k = 0; k < 4; k++) {
        v[k].x = __expf(v[k].x - mx);
        v[k].y = __expf(v[k].y - mx);
        v[k].z = __expf(v[k].z - mx);
        v[k].w = __expf(v[k].w - mx);
        sum += (v[k].x + v[k].y) + (v[k].z + v[k].w);
    }
#pragma unroll
    for (int o = 16; o > 0; o >>= 1)
        sum += __shfl_xor_sync(0xffffffffu, sum, o);
    __syncthreads();               // red[] reuse
    if ((t & 31) == 0) red[t >> 5] = sum;
    __syncthreads();
    float tot = 0.0f;
#pragma unroll
    for (int i = 0; i < 8; i++) tot += red[i];

    const float inv = 1.0f / tot;
#pragma unroll
    for (int k = 0; k < 4; k++) {
        v[k].x *= inv; v[k].y *= inv; v[k].z *= inv; v[k].w *= inv;
        p[t + 256 * k] = v[k];
    }
}

// ---------------------------------------------------------------------------
extern "C" void kernel_launch(void* const* d_in, const int* in_sizes, int n_in,
                              void* d_out, int out_size)
{
    const float* X  = (const float*)d_in[0];
    const float* Wq = (const float*)d_in[1];
    const float* bq = (const float*)d_in[2];
    const float* Wk = (const float*)d_in[3];
    const float* bk = (const float*)d_in[4];
    const float* Wv = (const float*)d_in[5];
    const float* bv = (const float*)d_in[6];
    float* out = (float*)d_out;

    float *Q, *Kd, *V, *S;
    cudaGetSymbolAddress((void**)&Q,  g_Q);
    cudaGetSymbolAddress((void**)&Kd, g_K);
    cudaGetSymbolAddress((void**)&V,  g_V);
    cudaGetSymbolAddress((void**)&S,  g_S);

    dim3 blk(256);

    // QKV projections: X[4096,1024] @ W[1024,1024]^T + b
    dim3 gP(DIM / 128, SEQ / 128);                 // 8 x 32
    gemm128<true, true><<<gP, blk>>>(X, Wq, bq, Q,  DIM, DIM, 1.0f);
    gemm128<true, true><<<gP, blk>>>(X, Wk, bk, Kd, DIM, DIM, 1.0f);
    gemm128<true, true><<<gP, blk>>>(X, Wv, bv, V,  DIM, DIM, 1.0f);

    // scores = (Q @ K^T) / sqrt(1024)
    dim3 gS(SEQ / 128, SEQ / 128);                 // 32 x 32
    gemm128<true, false><<<gS, blk>>>(Q, Kd, nullptr, S, SEQ, DIM, 0.03125f);

    // row softmax in place
    softmax4096<<<SEQ, 256>>>(S);

    // out = attn @ V   (NN: S[4096,4096] @ V[4096,1024])
    dim3 gO(DIM / 128, SEQ / 128);                 // 8 x 32
    gemm128<false, false><<<gO, blk>>>(S, V, nullptr, out, DIM, SEQ, 1.0f);
}

// round 6
// speedup vs baseline: 2.9991x; 2.9991x over previous
#include <cuda_runtime.h>
#include <cstdint>
#include <math.h>

#define SEQ 4096
#define DIM 1024

// ---------------- static device scratch (no allocation APIs) ----------------
__device__ float g_Q [SEQ * DIM];
__device__ float g_K [SEQ * DIM];
__device__ float g_VT[SEQ * DIM];                // V transposed: [DIM][SEQ]
__device__ float g_S [(size_t)SEQ * SEQ];        // scores / probs
__device__ float g_Xr[SEQ * DIM];                // tf32-rounded X
__device__ float g_Wr[3 * DIM * DIM];            // tf32-rounded Wq,Wk,Wv

// ---------------- helpers ----------------
__device__ __forceinline__ uint32_t smem_u32(const void* p) {
    uint32_t a;
    asm("{ .reg .u64 t; cvta.to.shared.u64 t, %1; cvt.u32.u64 %0, t; }" : "=r"(a) : "l"(p));
    return a;
}
__device__ __forceinline__ float tf32r(float x) {
    float y;
    asm("cvt.rna.tf32.f32 %0, %1;" : "=f"(y) : "f"(x));
    return y;
}
#define CP_COMMIT() asm volatile("cp.async.commit_group;" ::: "memory")
#define CP_WAIT(n)  asm volatile("cp.async.wait_group %0;" :: "n"(n) : "memory")

__device__ __forceinline__ void mma_tf32(float* d, const uint32_t* a, const uint32_t* b) {
    asm volatile(
        "mma.sync.aligned.m16n8k8.row.col.f32.tf32.tf32.f32 "
        "{%0,%1,%2,%3}, {%4,%5,%6,%7}, {%8,%9}, {%0,%1,%2,%3};"
        : "+f"(d[0]), "+f"(d[1]), "+f"(d[2]), "+f"(d[3])
        : "r"(a[0]), "r"(a[1]), "r"(a[2]), "r"(a[3]), "r"(b[0]), "r"(b[1]));
}

// ---------------- tile geometry ----------------
// BM=128, BN=128, BK=32. smem rows word-stride 36 (conflict-free frag loads).
static constexpr int STAGES       = 4;
static constexpr int STRIDE       = 36;                    // words per smem row
static constexpr int STAGE_FLOATS = 256 * STRIDE;          // A[128]+B[128] rows
static constexpr int STAGE_BYTES  = STAGE_FLOATS * 4;      // 36864
static constexpr int SMEM_TOTAL   = STAGES * STAGE_BYTES;  // 147456

// ---------------------------------------------------------------------------
// NT GEMM: C[M,N] = alpha * A[M,K] * B[N,K]^T (+ bias), tf32 mma.sync.
// A,B both K-major. Grid: (N/128, M/128), 256 threads (8 warps, 4m x 2n).
// BIAS_ROW: bias indexed by output row (for VT = Wv @ X^T), else by column.
// ---------------------------------------------------------------------------
template <bool HAS_BIAS, bool BIAS_ROW, bool ROUND_OUT>
__global__ __launch_bounds__(256, 1)
void mma_gemm(const float* __restrict__ A, const float* __restrict__ B,
              const float* __restrict__ bias, float* __restrict__ C,
              int Kdim, int ldc, float alpha)
{
    extern __shared__ float sm[];
    const int tid  = threadIdx.x;
    const int lane = tid & 31;
    const int wid  = tid >> 5;
    const int wm   = wid & 3;          // warp m: 0..3 (32 rows each)
    const int wn   = wid >> 2;         // warp n: 0..1 (64 cols each)
    const int lm   = lane >> 2;        // 0..7
    const int lc   = lane & 3;         // 0..3
    const int by   = blockIdx.y * 128;
    const int bx   = blockIdx.x * 128;

    const uint32_t sbase = smem_u32(sm);
    const float* Abase = A + (size_t)by * Kdim;
    const float* Bbase = B + (size_t)bx * Kdim;

    float acc[2][8][4];
#pragma unroll
    for (int mt = 0; mt < 2; mt++)
#pragma unroll
        for (int nt = 0; nt < 8; nt++)
#pragma unroll
            for (int q = 0; q < 4; q++) acc[mt][nt][q] = 0.0f;

    const int NK = Kdim >> 5;          // K chunks of 32

    // per-thread cp.async mapping: 4 A-chunks + 4 B-chunks of 16B per stage
    const int ldRow = tid >> 3;        // 0..31 base row group
    const int ldC16 = tid & 7;         // 0..7 (16B column)

#define LOAD_STAGE(chunk, stg) do {                                              \
    const int _k0 = (chunk) * 32;                                                \
    const uint32_t _s = sbase + (stg) * STAGE_BYTES;                             \
    _Pragma("unroll")                                                            \
    for (int _i = 0; _i < 4; _i++) {                                             \
        const int _row = _i * 32 + ldRow;                                        \
        const uint32_t _dst = _s + (uint32_t)(_row * STRIDE + ldC16 * 4) * 4;    \
        const float* _g = Abase + (size_t)_row * Kdim + _k0 + ldC16 * 4;         \
        asm volatile("cp.async.cg.shared.global [%0], [%1], 16;"                 \
                     :: "r"(_dst), "l"(_g) : "memory");                          \
    }                                                                            \
    _Pragma("unroll")                                                            \
    for (int _i = 0; _i < 4; _i++) {                                             \
        const int _row = _i * 32 + ldRow;                                        \
        const uint32_t _dst = _s + (uint32_t)((128 + _row) * STRIDE + ldC16 * 4) * 4; \
        const float* _g = Bbase + (size_t)_row * Kdim + _k0 + ldC16 * 4;         \
        asm volatile("cp.async.cg.shared.global [%0], [%1], 16;"                 \
                     :: "r"(_dst), "l"(_g) : "memory");                          \
    }                                                                            \
} while (0)

    // prologue: fill STAGES-1 stages
#pragma unroll
    for (int s = 0; s < STAGES - 1; s++) {
        if (s < NK) LOAD_STAGE(s, s);
        CP_COMMIT();
    }

    for (int c = 0; c < NK; c++) {
        CP_WAIT(STAGES - 2);
        __syncthreads();                       // chunk c resident

        const float* sA = sm + (c % STAGES) * STAGE_FLOATS;
        const float* sB = sA + 128 * STRIDE;
        const float* pA = sA + (wm * 32 + lm) * STRIDE + lc;
        const float* pB = sB + (wn * 64 + lm) * STRIDE + lc;

#pragma unroll
        for (int ks = 0; ks < 4; ks++) {       // 4 x k8 slices
            uint32_t afr[2][4], bfr[8][2];
#pragma unroll
            for (int mt = 0; mt < 2; mt++) {
                const float* p = pA + mt * 16 * STRIDE + ks * 8;
                afr[mt][0] = __float_as_uint(p[0]);
                afr[mt][1] = __float_as_uint(p[8 * STRIDE]);
                afr[mt][2] = __float_as_uint(p[4]);
                afr[mt][3] = __float_as_uint(p[8 * STRIDE + 4]);
            }
#pragma unroll
            for (int nt = 0; nt < 8; nt++) {
                const float* p = pB + nt * 8 * STRIDE + ks * 8;
                bfr[nt][0] = __float_as_uint(p[0]);
                bfr[nt][1] = __float_as_uint(p[4]);
            }
#pragma unroll
            for (int mt = 0; mt < 2; mt++)
#pragma unroll
                for (int nt = 0; nt < 8; nt++)
                    mma_tf32(acc[mt][nt], afr[mt], bfr[nt]);
        }
        __syncthreads();                       // stage free for reuse

        const int nc = c + STAGES - 1;
        if (nc < NK) LOAD_STAGE(nc, nc % STAGES);
        CP_COMMIT();
    }
#undef LOAD_STAGE

    // ---- epilogue ----
#pragma unroll
    for (int mt = 0; mt < 2; mt++) {
        const int row0 = by + wm * 32 + mt * 16 + lm;   // and row0+8
        float brow0 = 0.0f, brow1 = 0.0f;
        if (HAS_BIAS && BIAS_ROW) { brow0 = bias[row0]; brow1 = bias[row0 + 8]; }
#pragma unroll
        for (int nt = 0; nt < 8; nt++) {
            const int col = bx + wn * 64 + nt * 8 + lc * 2;
            float v0 = acc[mt][nt][0] * alpha;
            float v1 = acc[mt][nt][1] * alpha;
            float v2 = acc[mt][nt][2] * alpha;
            float v3 = acc[mt][nt][3] * alpha;
            if (HAS_BIAS) {
                if (BIAS_ROW) { v0 += brow0; v1 += brow0; v2 += brow1; v3 += brow1; }
                else {
                    const float bc0 = bias[col], bc1 = bias[col + 1];
                    v0 += bc0; v1 += bc1; v2 += bc0; v3 += bc1;
                }
            }
            if (ROUND_OUT) { v0 = tf32r(v0); v1 = tf32r(v1); v2 = tf32r(v2); v3 = tf32r(v3); }
            *(float2*)(C + (size_t)row0 * ldc + col)       = make_float2(v0, v1);
            *(float2*)(C + (size_t)(row0 + 8) * ldc + col) = make_float2(v2, v3);
        }
    }
}

// ---------------------------------------------------------------------------
// Elementwise round-to-tf32 (rna) pre-pass.
// ---------------------------------------------------------------------------
__global__ void round_tf32_kernel(const float* __restrict__ in, float* __restrict__ out) {
    int i = (blockIdx.x * blockDim.x + threadIdx.x) * 4;
    float4 v = *(const float4*)(in + i);
    v.x = tf32r(v.x); v.y = tf32r(v.y); v.z = tf32r(v.z); v.w = tf32r(v.w);
    *(float4*)(out + i) = v;
}

// ---------------------------------------------------------------------------
// Row softmax over 4096-wide rows, in place, output rounded to tf32.
// ---------------------------------------------------------------------------
__global__ void softmax4096(float* __restrict__ S) {
    const int row = blockIdx.x;
    float4* p = (float4*)(S + (size_t)row * SEQ);
    const int t = threadIdx.x;

    float4 v[4];
    float mx = -1e30f;
#pragma unroll
    for (int k = 0; k < 4; k++) {
        v[k] = p[t + 256 * k];
        mx = fmaxf(mx, fmaxf(fmaxf(v[k].x, v[k].y), fmaxf(v[k].z, v[k].w)));
    }
#pragma unroll
    for (int o = 16; o > 0; o >>= 1) mx = fmaxf(mx, __shfl_xor_sync(0xffffffffu, mx, o));

    __shared__ float red[8];
    if ((t & 31) == 0) red[t >> 5] = mx;
    __syncthreads();
    mx = red[0];
#pragma unroll
    for (int i = 1; i < 8; i++) mx = fmaxf(mx, red[i]);

    float sum = 0.0f;
#pragma unroll
    for (int k = 0; k < 4; k++) {
        v[k].x = __expf(v[k].x - mx);
        v[k].y = __expf(v[k].y - mx);
        v[k].z = __expf(v[k].z - mx);
        v[k].w = __expf(v[k].w - mx);
        sum += (v[k].x + v[k].y) + (v[k].z + v[k].w);
    }
#pragma unroll
    for (int o = 16; o > 0; o >>= 1) sum += __shfl_xor_sync(0xffffffffu, sum, o);
    __syncthreads();
    if ((t & 31) == 0) red[t >> 5] = sum;
    __syncthreads();
    float tot = 0.0f;
#pragma unroll
    for (int i = 0; i < 8; i++) tot += red[i];

    const float inv = 1.0f / tot;
#pragma unroll
    for (int k = 0; k < 4; k++) {
        v[k].x = tf32r(v[k].x * inv); v[k].y = tf32r(v[k].y * inv);
        v[k].z = tf32r(v[k].z * inv); v[k].w = tf32r(v[k].w * inv);
        p[t + 256 * k] = v[k];
    }
}

// ---------------------------------------------------------------------------
extern "C" void kernel_launch(void* const* d_in, const int* in_sizes, int n_in,
                              void* d_out, int out_size)
{
    const float* X  = (const float*)d_in[0];
    const float* Wq = (const float*)d_in[1];
    const float* bq = (const float*)d_in[2];
    const float* Wk = (const float*)d_in[3];
    const float* bk = (const float*)d_in[4];
    const float* Wv = (const float*)d_in[5];
    const float* bv = (const float*)d_in[6];
    float* out = (float*)d_out;

    float *Q, *Kd, *VT, *S, *Xr, *Wr;
    cudaGetSymbolAddress((void**)&Q,  g_Q);
    cudaGetSymbolAddress((void**)&Kd, g_K);
    cudaGetSymbolAddress((void**)&VT, g_VT);
    cudaGetSymbolAddress((void**)&S,  g_S);
    cudaGetSymbolAddress((void**)&Xr, g_Xr);
    cudaGetSymbolAddress((void**)&Wr, g_Wr);
    float* Wqr = Wr;
    float* Wkr = Wr + (size_t)DIM * DIM;
    float* Wvr = Wr + (size_t)2 * DIM * DIM;

    cudaFuncSetAttribute(mma_gemm<true,  false, true >, cudaFuncAttributeMaxDynamicSharedMemorySize, SMEM_TOTAL);
    cudaFuncSetAttribute(mma_gemm<true,  true,  true >, cudaFuncAttributeMaxDynamicSharedMemorySize, SMEM_TOTAL);
    cudaFuncSetAttribute(mma_gemm<false, false, true >, cudaFuncAttributeMaxDynamicSharedMemorySize, SMEM_TOTAL);
    cudaFuncSetAttribute(mma_gemm<false, false, false>, cudaFuncAttributeMaxDynamicSharedMemorySize, SMEM_TOTAL);

    // pre-round MMA operands to tf32 (rna) — removes truncation bias
    round_tf32_kernel<<<SEQ * DIM / 1024, 256>>>(X,  Xr);
    round_tf32_kernel<<<DIM * DIM / 1024, 256>>>(Wq, Wqr);
    round_tf32_kernel<<<DIM * DIM / 1024, 256>>>(Wk, Wkr);
    round_tf32_kernel<<<DIM * DIM / 1024, 256>>>(Wv, Wvr);

    dim3 blk(256);

    // Q = Xr @ Wq^T + bq        [4096,1024]  grid (N/128, M/128)
    dim3 gQK(DIM / 128, SEQ / 128);
    mma_gemm<true, false, true ><<<gQK, blk, SMEM_TOTAL>>>(Xr, Wqr, bq, Q,  DIM, DIM, 1.0f);
    mma_gemm<true, false, true ><<<gQK, blk, SMEM_TOTAL>>>(Xr, Wkr, bk, Kd, DIM, DIM, 1.0f);

    // VT = Wv @ X^T + bv(row)   [1024,4096]  (A=Wv rows=DIM, B=X rows=SEQ)
    dim3 gVT(SEQ / 128, DIM / 128);
    mma_gemm<true, true,  true ><<<gVT, blk, SMEM_TOTAL>>>(Wvr, Xr, bv, VT, DIM, SEQ, 1.0f);

    // S = (Q @ K^T) / 32        [4096,4096]
    dim3 gS(SEQ / 128, SEQ / 128);
    mma_gemm<false, false, true ><<<gS, blk, SMEM_TOTAL>>>(Q, Kd, nullptr, S, DIM, SEQ, 0.03125f);

    // softmax rows, tf32-rounded
    softmax4096<<<SEQ, 256>>>(S);

    // out = P @ V = P @ (VT)^T  [4096,1024]  (B=VT rows=DIM, K=SEQ)
    dim3 gO(DIM / 128, SEQ / 128);
    mma_gemm<false, false, false><<<gO, blk, SMEM_TOTAL>>>(S, VT, nullptr, out, SEQ, DIM, 1.0f);
}

// round 7
// speedup vs baseline: 3.6838x; 1.2283x over previous
#include <cuda_runtime.h>
#include <cstdint>
#include <math.h>

#define SEQ 4096
#define DIM 1024

// ---------------- static device scratch (no allocation APIs) ----------------
__device__ float g_Q [SEQ * DIM];
__device__ float g_K [SEQ * DIM];
__device__ float g_VT[SEQ * DIM];                // V transposed: [DIM][SEQ]
__device__ float g_S [(size_t)SEQ * SEQ];        // scores / probs
__device__ float g_Xr[SEQ * DIM];                // tf32-rounded X
__device__ float g_Wr[3 * DIM * DIM];            // tf32-rounded Wq,Wk,Wv

// ---------------- helpers ----------------
__device__ __forceinline__ uint32_t smem_u32(const void* p) {
    uint32_t a;
    asm("{ .reg .u64 t; cvta.to.shared.u64 t, %1; cvt.u32.u64 %0, t; }" : "=r"(a) : "l"(p));
    return a;
}
__device__ __forceinline__ float tf32r(float x) {
    float y;
    asm("cvt.rna.tf32.f32 %0, %1;" : "=f"(y) : "f"(x));
    return y;
}
#define CP_COMMIT() asm volatile("cp.async.commit_group;" ::: "memory")
#define CP_WAIT(n)  asm volatile("cp.async.wait_group %0;" :: "n"(n) : "memory")

__device__ __forceinline__ void mma_tf32(float* d, const uint32_t* a, const uint32_t* b) {
    asm volatile(
        "mma.sync.aligned.m16n8k8.row.col.f32.tf32.tf32.f32 "
        "{%0,%1,%2,%3}, {%4,%5,%6,%7}, {%8,%9}, {%0,%1,%2,%3};"
        : "+f"(d[0]), "+f"(d[1]), "+f"(d[2]), "+f"(d[3])
        : "r"(a[0]), "r"(a[1]), "r"(a[2]), "r"(a[3]), "r"(b[0]), "r"(b[1]));
}

// ---------------- tile geometry ----------------
// Block 256x128, BK=32. 8 warps (4m x 2n), warp tile 64x64.
// smem rows word-stride 36 -> conflict-free scalar fragment loads.
static constexpr int BM           = 256;
static constexpr int BN           = 128;
static constexpr int STAGES       = 3;
static constexpr int STRIDE       = 36;                     // words per smem row
static constexpr int STAGE_FLOATS = (BM + BN) * STRIDE;     // 13824
static constexpr int STAGE_BYTES  = STAGE_FLOATS * 4;       // 55296
static constexpr int SMEM_TOTAL   = STAGES * STAGE_BYTES;   // 165888

// ---------------------------------------------------------------------------
// NT GEMM: C[M,N] = alpha * A[M,K] * B[N,K]^T (+ bias), tf32 mma.sync.
// A,B both K-major. Grid: (N/128, M/256), 256 threads.
// BIAS_ROW: bias indexed by output row (for VT = Wv @ X^T), else by column.
// ---------------------------------------------------------------------------
template <bool HAS_BIAS, bool BIAS_ROW, bool ROUND_OUT>
__global__ __launch_bounds__(256, 1)
void mma_gemm(const float* __restrict__ A, const float* __restrict__ B,
              const float* __restrict__ bias, float* __restrict__ C,
              int Kdim, int ldc, float alpha)
{
    extern __shared__ float sm[];
    const int tid  = threadIdx.x;
    const int lane = tid & 31;
    const int wid  = tid >> 5;
    const int wm   = wid & 3;          // warp m: 0..3 (64 rows each)
    const int wn   = wid >> 2;         // warp n: 0..1 (64 cols each)
    const int lm   = lane >> 2;        // 0..7
    const int lc   = lane & 3;         // 0..3
    const int by   = blockIdx.y * BM;
    const int bx   = blockIdx.x * BN;

    const uint32_t sbase = smem_u32(sm);
    const float* Abase = A + (size_t)by * Kdim;
    const float* Bbase = B + (size_t)bx * Kdim;

    float acc[4][8][4];                // 4 mt x 8 nt x 4 regs = 128
#pragma unroll
    for (int mt = 0; mt < 4; mt++)
#pragma unroll
        for (int nt = 0; nt < 8; nt++)
#pragma unroll
            for (int q = 0; q < 4; q++) acc[mt][nt][q] = 0.0f;

    const int NK = Kdim >> 5;          // K chunks of 32

    // cp.async mapping: 256 threads, 16B each. A: 256 rows x 8 cols (8 iters),
    // B: 128 rows x 8 cols (4 iters).
    const int ldRow = tid >> 3;        // 0..31
    const int ldC16 = tid & 7;         // 0..7

#define LOAD_STAGE(chunk, stg) do {                                              \
    const int _k0 = (chunk) * 32;                                                \
    const uint32_t _s = sbase + (stg) * STAGE_BYTES;                             \
    _Pragma("unroll")                                                            \
    for (int _i = 0; _i < 8; _i++) {                                             \
        const int _row = _i * 32 + ldRow;                                        \
        const uint32_t _dst = _s + (uint32_t)(_row * STRIDE + ldC16 * 4) * 4;    \
        const float* _g = Abase + (size_t)_row * Kdim + _k0 + ldC16 * 4;         \
        asm volatile("cp.async.cg.shared.global [%0], [%1], 16;"                 \
                     :: "r"(_dst), "l"(_g) : "memory");                          \
    }                                                                            \
    _Pragma("unroll")                                                            \
    for (int _i = 0; _i < 4; _i++) {                                             \
        const int _row = _i * 32 + ldRow;                                        \
        const uint32_t _dst = _s + (uint32_t)((BM + _row) * STRIDE + ldC16 * 4) * 4; \
        const float* _g = Bbase + (size_t)_row * Kdim + _k0 + ldC16 * 4;         \
        asm volatile("cp.async.cg.shared.global [%0], [%1], 16;"                 \
                     :: "r"(_dst), "l"(_g) : "memory");                          \
    }                                                                            \
} while (0)

    // prologue: fill STAGES-1 stages
#pragma unroll
    for (int s = 0; s < STAGES - 1; s++) {
        if (s < NK) LOAD_STAGE(s, s);
        CP_COMMIT();
    }

    for (int c = 0; c < NK; c++) {
        CP_WAIT(STAGES - 2);
        __syncthreads();               // chunk c resident; stage (c-1)%S free

        const float* sA = sm + (c % STAGES) * STAGE_FLOATS;
        const float* sB = sA + BM * STRIDE;
        const float* pA = sA + (wm * 64 + lm) * STRIDE + lc;
        const float* pB = sB + (wn * 64 + lm) * STRIDE + lc;

#pragma unroll
        for (int ks = 0; ks < 4; ks++) {       // 4 x k8 slices
            uint32_t afr[4][4], bfr[8][2];
#pragma unroll
            for (int mt = 0; mt < 4; mt++) {
                const float* p = pA + mt * 16 * STRIDE + ks * 8;
                afr[mt][0] = __float_as_uint(p[0]);
                afr[mt][1] = __float_as_uint(p[8 * STRIDE]);
                afr[mt][2] = __float_as_uint(p[4]);
                afr[mt][3] = __float_as_uint(p[8 * STRIDE + 4]);
            }
#pragma unroll
            for (int nt = 0; nt < 8; nt++) {
                const float* p = pB + nt * 8 * STRIDE + ks * 8;
                bfr[nt][0] = __float_as_uint(p[0]);
                bfr[nt][1] = __float_as_uint(p[4]);
            }
#pragma unroll
            for (int mt = 0; mt < 4; mt++)
#pragma unroll
                for (int nt = 0; nt < 8; nt++)
                    mma_tf32(acc[mt][nt], afr[mt], bfr[nt]);
        }

        const int nc = c + STAGES - 1;
        if (nc < NK) LOAD_STAGE(nc, nc % STAGES);
        CP_COMMIT();
    }
#undef LOAD_STAGE

    // ---- epilogue ----
#pragma unroll
    for (int mt = 0; mt < 4; mt++) {
        const int row0 = by + wm * 64 + mt * 16 + lm;   // and row0+8
        float brow0 = 0.0f, brow1 = 0.0f;
        if (HAS_BIAS && BIAS_ROW) { brow0 = bias[row0]; brow1 = bias[row0 + 8]; }
#pragma unroll
        for (int nt = 0; nt < 8; nt++) {
            const int col = bx + wn * 64 + nt * 8 + lc * 2;
            float v0 = acc[mt][nt][0] * alpha;
            float v1 = acc[mt][nt][1] * alpha;
            float v2 = acc[mt][nt][2] * alpha;
            float v3 = acc[mt][nt][3] * alpha;
            if (HAS_BIAS) {
                if (BIAS_ROW) { v0 += brow0; v1 += brow0; v2 += brow1; v3 += brow1; }
                else {
                    const float bc0 = bias[col], bc1 = bias[col + 1];
                    v0 += bc0; v1 += bc1; v2 += bc0; v3 += bc1;
                }
            }
            if (ROUND_OUT) { v0 = tf32r(v0); v1 = tf32r(v1); v2 = tf32r(v2); v3 = tf32r(v3); }
            *(float2*)(C + (size_t)row0 * ldc + col)       = make_float2(v0, v1);
            *(float2*)(C + (size_t)(row0 + 8) * ldc + col) = make_float2(v2, v3);
        }
    }
}

// ---------------------------------------------------------------------------
// Elementwise round-to-tf32 (rna) pre-pass.
// ---------------------------------------------------------------------------
__global__ void round_tf32_kernel(const float* __restrict__ in, float* __restrict__ out) {
    int i = (blockIdx.x * blockDim.x + threadIdx.x) * 4;
    float4 v = *(const float4*)(in + i);
    v.x = tf32r(v.x); v.y = tf32r(v.y); v.z = tf32r(v.z); v.w = tf32r(v.w);
    *(float4*)(out + i) = v;
}

// ---------------------------------------------------------------------------
// Row softmax over 4096-wide rows, in place, output rounded to tf32.
// ---------------------------------------------------------------------------
__global__ void softmax4096(float* __restrict__ S) {
    const int row = blockIdx.x;
    float4* p = (float4*)(S + (size_t)row * SEQ);
    const int t = threadIdx.x;

    float4 v[4];
    float mx = -1e30f;
#pragma unroll
    for (int k = 0; k < 4; k++) {
        v[k] = p[t + 256 * k];
        mx = fmaxf(mx, fmaxf(fmaxf(v[k].x, v[k].y), fmaxf(v[k].z, v[k].w)));
    }
#pragma unroll
    for (int o = 16; o > 0; o >>= 1) mx = fmaxf(mx, __shfl_xor_sync(0xffffffffu, mx, o));

    __shared__ float red[8];
    if ((t & 31) == 0) red[t >> 5] = mx;
    __syncthreads();
    mx = red[0];
#pragma unroll
    for (int i = 1; i < 8; i++) mx = fmaxf(mx, red[i]);

    float sum = 0.0f;
#pragma unroll
    for (int k = 0; k < 4; k++) {
        v[k].x = __expf(v[k].x - mx);
        v[k].y = __expf(v[k].y - mx);
        v[k].z = __expf(v[k].z - mx);
        v[k].w = __expf(v[k].w - mx);
        sum += (v[k].x + v[k].y) + (v[k].z + v[k].w);
    }
#pragma unroll
    for (int o = 16; o > 0; o >>= 1) sum += __shfl_xor_sync(0xffffffffu, sum, o);
    __syncthreads();
    if ((t & 31) == 0) red[t >> 5] = sum;
    __syncthreads();
    float tot = 0.0f;
#pragma unroll
    for (int i = 0; i < 8; i++) tot += red[i];

    const float inv = 1.0f / tot;
#pragma unroll
    for (int k = 0; k < 4; k++) {
        v[k].x = tf32r(v[k].x * inv); v[k].y = tf32r(v[k].y * inv);
        v[k].z = tf32r(v[k].z * inv); v[k].w = tf32r(v[k].w * inv);
        p[t + 256 * k] = v[k];
    }
}

// ---------------------------------------------------------------------------
extern "C" void kernel_launch(void* const* d_in, const int* in_sizes, int n_in,
                              void* d_out, int out_size)
{
    const float* X  = (const float*)d_in[0];
    const float* Wq = (const float*)d_in[1];
    const float* bq = (const float*)d_in[2];
    const float* Wk = (const float*)d_in[3];
    const float* bk = (const float*)d_in[4];
    const float* Wv = (const float*)d_in[5];
    const float* bv = (const float*)d_in[6];
    float* out = (float*)d_out;

    float *Q, *Kd, *VT, *S, *Xr, *Wr;
    cudaGetSymbolAddress((void**)&Q,  g_Q);
    cudaGetSymbolAddress((void**)&Kd, g_K);
    cudaGetSymbolAddress((void**)&VT, g_VT);
    cudaGetSymbolAddress((void**)&S,  g_S);
    cudaGetSymbolAddress((void**)&Xr, g_Xr);
    cudaGetSymbolAddress((void**)&Wr, g_Wr);
    float* Wqr = Wr;
    float* Wkr = Wr + (size_t)DIM * DIM;
    float* Wvr = Wr + (size_t)2 * DIM * DIM;

    cudaFuncSetAttribute(mma_gemm<true,  false, true >, cudaFuncAttributeMaxDynamicSharedMemorySize, SMEM_TOTAL);
    cudaFuncSetAttribute(mma_gemm<true,  true,  true >, cudaFuncAttributeMaxDynamicSharedMemorySize, SMEM_TOTAL);
    cudaFuncSetAttribute(mma_gemm<false, false, true >, cudaFuncAttributeMaxDynamicSharedMemorySize, SMEM_TOTAL);
    cudaFuncSetAttribute(mma_gemm<false, false, false>, cudaFuncAttributeMaxDynamicSharedMemorySize, SMEM_TOTAL);

    // pre-round MMA operands to tf32 (rna) — removes truncation bias
    round_tf32_kernel<<<SEQ * DIM / 1024, 256>>>(X,  Xr);
    round_tf32_kernel<<<DIM * DIM / 1024, 256>>>(Wq, Wqr);
    round_tf32_kernel<<<DIM * DIM / 1024, 256>>>(Wk, Wkr);
    round_tf32_kernel<<<DIM * DIM / 1024, 256>>>(Wv, Wvr);

    dim3 blk(256);

    // Q = Xr @ Wq^T + bq        [4096,1024]   grid (N/BN, M/BM)
    dim3 gQK(DIM / BN, SEQ / BM);            // (8, 16)
    mma_gemm<true, false, true ><<<gQK, blk, SMEM_TOTAL>>>(Xr, Wqr, bq, Q,  DIM, DIM, 1.0f);
    mma_gemm<true, false, true ><<<gQK, blk, SMEM_TOTAL>>>(Xr, Wkr, bk, Kd, DIM, DIM, 1.0f);

    // VT = Wv @ X^T + bv(row)   [1024,4096]
    dim3 gVT(SEQ / BN, DIM / BM);            // (32, 4)
    mma_gemm<true, true,  true ><<<gVT, blk, SMEM_TOTAL>>>(Wvr, Xr, bv, VT, DIM, SEQ, 1.0f);

    // S = (Q @ K^T) / 32        [4096,4096]
    dim3 gS(SEQ / BN, SEQ / BM);             // (32, 16)
    mma_gemm<false, false, true ><<<gS, blk, SMEM_TOTAL>>>(Q, Kd, nullptr, S, DIM, SEQ, 0.03125f);

    // softmax rows, tf32-rounded
    softmax4096<<<SEQ, 256>>>(S);

    // out = P @ V = P @ (VT)^T  [4096,1024]
    dim3 gO(DIM / BN, SEQ / BM);             // (8, 16)
    mma_gemm<false, false, false><<<gO, blk, SMEM_TOTAL>>>(S, VT, nullptr, out, SEQ, DIM, 1.0f);
}

// round 8
// speedup vs baseline: 6.6861x; 1.8150x over previous
#include <cuda_runtime.h>
#include <cuda_fp16.h>
#include <cstdint>
#include <math.h>

#define SEQ 4096
#define DIM 1024

// ---------------- static device scratch (no allocation APIs) ----------------
__device__ __half g_Qh [SEQ * DIM];
__device__ __half g_Kh [SEQ * DIM];
__device__ __half g_VTh[SEQ * DIM];               // V transposed: [DIM][SEQ]
__device__ float  g_S  [(size_t)SEQ * SEQ];       // scores (fp32)
__device__ __half g_P  [(size_t)SEQ * SEQ];       // probs (fp16)
__device__ __half g_Xh [SEQ * DIM];               // fp16-rounded X
__device__ __half g_Wh [3 * DIM * DIM];           // fp16-rounded Wq,Wk,Wv

// ---------------- helpers ----------------
__device__ __forceinline__ uint32_t smem_u32(const void* p) {
    uint32_t a;
    asm("{ .reg .u64 t; cvta.to.shared.u64 t, %1; cvt.u32.u64 %0, t; }" : "=r"(a) : "l"(p));
    return a;
}
#define CP_COMMIT() asm volatile("cp.async.commit_group;" ::: "memory")
#define CP_WAIT(n)  asm volatile("cp.async.wait_group %0;" :: "n"(n) : "memory")

__device__ __forceinline__ void mma_f16(float* d, const uint32_t* a, const uint32_t* b) {
    asm volatile(
        "mma.sync.aligned.m16n8k16.row.col.f32.f16.f16.f32 "
        "{%0,%1,%2,%3}, {%4,%5,%6,%7}, {%8,%9}, {%0,%1,%2,%3};"
        : "+f"(d[0]), "+f"(d[1]), "+f"(d[2]), "+f"(d[3])
        : "r"(a[0]), "r"(a[1]), "r"(a[2]), "r"(a[3]), "r"(b[0]), "r"(b[1]));
}

// ---------------- tile geometry ----------------
// Block 256x128, BK=64 halves. 8 warps (4m x 2n), warp tile 64x64.
// smem rows: 64 data halves + 8 pad = 72 halves (word-stride 36 -> conflict-free).
static constexpr int BM           = 256;
static constexpr int BN           = 128;
static constexpr int STAGES       = 3;
static constexpr int STRIDE_H     = 72;                     // halves per smem row
static constexpr int STAGE_HALVES = (BM + BN) * STRIDE_H;   // 27648
static constexpr int STAGE_BYTES  = STAGE_HALVES * 2;       // 55296
static constexpr int SMEM_TOTAL   = STAGES * STAGE_BYTES;   // 165888

// ---------------------------------------------------------------------------
// NT GEMM: C[M,N] = alpha * A[M,K] * B[N,K]^T (+ bias), fp16 mma, fp32 accum.
// A,B half, K-major. Grid: (N/BN, M/BM), 256 threads.
// STORE_HALF: C is __half, else float.  BIAS_ROW: bias indexed by output row.
// ---------------------------------------------------------------------------
template <bool HAS_BIAS, bool BIAS_ROW, bool STORE_HALF>
__global__ __launch_bounds__(256, 1)
void mma_gemm_h(const __half* __restrict__ A, const __half* __restrict__ B,
                const float* __restrict__ bias, void* __restrict__ Cv,
                int Kdim, int ldc, float alpha)
{
    extern __shared__ __half sm[];
    const int tid  = threadIdx.x;
    const int lane = tid & 31;
    const int wid  = tid >> 5;
    const int wm   = wid & 3;          // warp m: 0..3 (64 rows each)
    const int wn   = wid >> 2;         // warp n: 0..1 (64 cols each)
    const int lm   = lane >> 2;        // 0..7
    const int lc   = lane & 3;         // 0..3
    const int by   = blockIdx.y * BM;
    const int bx   = blockIdx.x * BN;

    const uint32_t sbase = smem_u32(sm);
    const __half* Abase = A + (size_t)by * Kdim;
    const __half* Bbase = B + (size_t)bx * Kdim;

    float acc[4][8][4];
#pragma unroll
    for (int mt = 0; mt < 4; mt++)
#pragma unroll
        for (int nt = 0; nt < 8; nt++)
#pragma unroll
            for (int q = 0; q < 4; q++) acc[mt][nt][q] = 0.0f;

    const int NK = Kdim >> 6;          // K chunks of 64 halves

    // cp.async mapping: 16B = 8 halves per op. A: 256 rows x 8 (8 iters),
    // B: 128 rows x 8 (4 iters).
    const int ldRow = tid >> 3;        // 0..31
    const int ldC16 = tid & 7;         // 0..7

#define LOAD_STAGE(chunk, stg) do {                                              \
    const int _k0 = (chunk) * 64;                                                \
    const uint32_t _s = sbase + (stg) * STAGE_BYTES;                             \
    _Pragma("unroll")                                                            \
    for (int _i = 0; _i < 8; _i++) {                                             \
        const int _row = _i * 32 + ldRow;                                        \
        const uint32_t _dst = _s + (uint32_t)(_row * STRIDE_H + ldC16 * 8) * 2;  \
        const __half* _g = Abase + (size_t)_row * Kdim + _k0 + ldC16 * 8;        \
        asm volatile("cp.async.cg.shared.global [%0], [%1], 16;"                 \
                     :: "r"(_dst), "l"(_g) : "memory");                          \
    }                                                                            \
    _Pragma("unroll")                                                            \
    for (int _i = 0; _i < 4; _i++) {                                             \
        const int _row = _i * 32 + ldRow;                                        \
        const uint32_t _dst = _s + (uint32_t)((BM + _row) * STRIDE_H + ldC16 * 8) * 2; \
        const __half* _g = Bbase + (size_t)_row * Kdim + _k0 + ldC16 * 8;        \
        asm volatile("cp.async.cg.shared.global [%0], [%1], 16;"                 \
                     :: "r"(_dst), "l"(_g) : "memory");                          \
    }                                                                            \
} while (0)

    // prologue: fill STAGES-1 stages
#pragma unroll
    for (int s = 0; s < STAGES - 1; s++) {
        if (s < NK) LOAD_STAGE(s, s);
        CP_COMMIT();
    }

    for (int c = 0; c < NK; c++) {
        CP_WAIT(STAGES - 2);
        __syncthreads();               // chunk c resident; stage (c-1)%S free

        const __half* sA = sm + (c % STAGES) * STAGE_HALVES;
        const __half* sB = sA + BM * STRIDE_H;
        const __half* pA = sA + (wm * 64 + lm) * STRIDE_H + 2 * lc;
        const __half* pB = sB + (wn * 64 + lm) * STRIDE_H + 2 * lc;

#pragma unroll
        for (int ks = 0; ks < 4; ks++) {       // 4 x k16 slices
            uint32_t afr[4][4], bfr[8][2];
#pragma unroll
            for (int mt = 0; mt < 4; mt++) {
                const __half* p = pA + mt * 16 * STRIDE_H + ks * 16;
                afr[mt][0] = *(const uint32_t*)(p);
                afr[mt][1] = *(const uint32_t*)(p + 8 * STRIDE_H);
                afr[mt][2] = *(const uint32_t*)(p + 8);
                afr[mt][3] = *(const uint32_t*)(p + 8 * STRIDE_H + 8);
            }
#pragma unroll
            for (int nt = 0; nt < 8; nt++) {
                const __half* p = pB + nt * 8 * STRIDE_H + ks * 16;
                bfr[nt][0] = *(const uint32_t*)(p);
                bfr[nt][1] = *(const uint32_t*)(p + 8);
            }
#pragma unroll
            for (int mt = 0; mt < 4; mt++)
#pragma unroll
                for (int nt = 0; nt < 8; nt++)
                    mma_f16(acc[mt][nt], afr[mt], bfr[nt]);
        }

        const int nc = c + STAGES - 1;
        if (nc < NK) LOAD_STAGE(nc, nc % STAGES);
        CP_COMMIT();
    }
#undef LOAD_STAGE

    // ---- epilogue ----
#pragma unroll
    for (int mt = 0; mt < 4; mt++) {
        const int row0 = by + wm * 64 + mt * 16 + lm;   // and row0+8
        float brow0 = 0.0f, brow1 = 0.0f;
        if (HAS_BIAS && BIAS_ROW) { brow0 = bias[row0]; brow1 = bias[row0 + 8]; }
#pragma unroll
        for (int nt = 0; nt < 8; nt++) {
            const int col = bx + wn * 64 + nt * 8 + lc * 2;
            float v0 = acc[mt][nt][0] * alpha;
            float v1 = acc[mt][nt][1] * alpha;
            float v2 = acc[mt][nt][2] * alpha;
            float v3 = acc[mt][nt][3] * alpha;
            if (HAS_BIAS) {
                if (BIAS_ROW) { v0 += brow0; v1 += brow0; v2 += brow1; v3 += brow1; }
                else {
                    const float bc0 = bias[col], bc1 = bias[col + 1];
                    v0 += bc0; v1 += bc1; v2 += bc0; v3 += bc1;
                }
            }
            if (STORE_HALF) {
                __half* C = (__half*)Cv;
                *(__half2*)(C + (size_t)row0 * ldc + col)       = __floats2half2_rn(v0, v1);
                *(__half2*)(C + (size_t)(row0 + 8) * ldc + col) = __floats2half2_rn(v2, v3);
            } else {
                float* C = (float*)Cv;
                *(float2*)(C + (size_t)row0 * ldc + col)       = make_float2(v0, v1);
                *(float2*)(C + (size_t)(row0 + 8) * ldc + col) = make_float2(v2, v3);
            }
        }
    }
}

// ---------------------------------------------------------------------------
// Elementwise fp32 -> fp16 (rne) pre-pass.
// ---------------------------------------------------------------------------
__global__ void f2h_kernel(const float* __restrict__ in, __half* __restrict__ out) {
    int i = (blockIdx.x * blockDim.x + threadIdx.x) * 4;
    float4 v = *(const float4*)(in + i);
    __half2 h0 = __floats2half2_rn(v.x, v.y);
    __half2 h1 = __floats2half2_rn(v.z, v.w);
    uint2 u;
    u.x = *(uint32_t*)&h0;
    u.y = *(uint32_t*)&h1;
    *(uint2*)(out + i) = u;
}

// ---------------------------------------------------------------------------
// Row softmax: S (fp32) -> P (fp16), 4096-wide rows, one block per row.
// ---------------------------------------------------------------------------
__global__ void softmax4096(const float* __restrict__ S, __half* __restrict__ P) {
    const int row = blockIdx.x;
    const float4* p = (const float4*)(S + (size_t)row * SEQ);
    __half* pp = P + (size_t)row * SEQ;
    const int t = threadIdx.x;

    float4 v[4];
    float mx = -1e30f;
#pragma unroll
    for (int k = 0; k < 4; k++) {
        v[k] = p[t + 256 * k];
        mx = fmaxf(mx, fmaxf(fmaxf(v[k].x, v[k].y), fmaxf(v[k].z, v[k].w)));
    }
#pragma unroll
    for (int o = 16; o > 0; o >>= 1) mx = fmaxf(mx, __shfl_xor_sync(0xffffffffu, mx, o));

    __shared__ float red[8];
    if ((t & 31) == 0) red[t >> 5] = mx;
    __syncthreads();
    mx = red[0];
#pragma unroll
    for (int i = 1; i < 8; i++) mx = fmaxf(mx, red[i]);

    float sum = 0.0f;
#pragma unroll
    for (int k = 0; k < 4; k++) {
        v[k].x = __expf(v[k].x - mx);
        v[k].y = __expf(v[k].y - mx);
        v[k].z = __expf(v[k].z - mx);
        v[k].w = __expf(v[k].w - mx);
        sum += (v[k].x + v[k].y) + (v[k].z + v[k].w);
    }
#pragma unroll
    for (int o = 16; o > 0; o >>= 1) sum += __shfl_xor_sync(0xffffffffu, sum, o);
    __syncthreads();
    if ((t & 31) == 0) red[t >> 5] = sum;
    __syncthreads();
    float tot = 0.0f;
#pragma unroll
    for (int i = 0; i < 8; i++) tot += red[i];

    const float inv = 1.0f / tot;
#pragma unroll
    for (int k = 0; k < 4; k++) {
        const int e = (t + 256 * k) * 4;
        __half2 h0 = __floats2half2_rn(v[k].x * inv, v[k].y * inv);
        __half2 h1 = __floats2half2_rn(v[k].z * inv, v[k].w * inv);
        uint2 u;
        u.x = *(uint32_t*)&h0;
        u.y = *(uint32_t*)&h1;
        *(uint2*)(pp + e) = u;
    }
}

// ---------------------------------------------------------------------------
extern "C" void kernel_launch(void* const* d_in, const int* in_sizes, int n_in,
                              void* d_out, int out_size)
{
    const float* X  = (const float*)d_in[0];
    const float* Wq = (const float*)d_in[1];
    const float* bq = (const float*)d_in[2];
    const float* Wk = (const float*)d_in[3];
    const float* bk = (const float*)d_in[4];
    const float* Wv = (const float*)d_in[5];
    const float* bv = (const float*)d_in[6];
    float* out = (float*)d_out;

    __half *Qh, *Kh, *VTh, *P, *Xh, *Wh;
    float *S;
    cudaGetSymbolAddress((void**)&Qh,  g_Qh);
    cudaGetSymbolAddress((void**)&Kh,  g_Kh);
    cudaGetSymbolAddress((void**)&VTh, g_VTh);
    cudaGetSymbolAddress((void**)&S,   g_S);
    cudaGetSymbolAddress((void**)&P,   g_P);
    cudaGetSymbolAddress((void**)&Xh,  g_Xh);
    cudaGetSymbolAddress((void**)&Wh,  g_Wh);
    __half* Wqh = Wh;
    __half* Wkh = Wh + (size_t)DIM * DIM;
    __half* Wvh = Wh + (size_t)2 * DIM * DIM;

    cudaFuncSetAttribute(mma_gemm_h<true,  false, true >, cudaFuncAttributeMaxDynamicSharedMemorySize, SMEM_TOTAL);
    cudaFuncSetAttribute(mma_gemm_h<true,  true,  true >, cudaFuncAttributeMaxDynamicSharedMemorySize, SMEM_TOTAL);
    cudaFuncSetAttribute(mma_gemm_h<false, false, false>, cudaFuncAttributeMaxDynamicSharedMemorySize, SMEM_TOTAL);

    // round inputs to fp16 (rne)
    f2h_kernel<<<SEQ * DIM / 1024, 256>>>(X,  Xh);
    f2h_kernel<<<DIM * DIM / 1024, 256>>>(Wq, Wqh);
    f2h_kernel<<<DIM * DIM / 1024, 256>>>(Wk, Wkh);
    f2h_kernel<<<DIM * DIM / 1024, 256>>>(Wv, Wvh);

    dim3 blk(256);

    // Q = Xh @ Wq^T + bq   [4096,1024] half
    dim3 gQK(DIM / BN, SEQ / BM);            // (8, 16)
    mma_gemm_h<true, false, true ><<<gQK, blk, SMEM_TOTAL>>>(Xh, Wqh, bq, Qh, DIM, DIM, 1.0f);
    mma_gemm_h<true, false, true ><<<gQK, blk, SMEM_TOTAL>>>(Xh, Wkh, bk, Kh, DIM, DIM, 1.0f);

    // VT = Wv @ X^T + bv(row)  [1024,4096] half
    dim3 gVT(SEQ / BN, DIM / BM);            // (32, 4)
    mma_gemm_h<true, true,  true ><<<gVT, blk, SMEM_TOTAL>>>(Wvh, Xh, bv, VTh, DIM, SEQ, 1.0f);

    // S = (Q @ K^T) / 32   [4096,4096] fp32
    dim3 gS(SEQ / BN, SEQ / BM);             // (32, 16)
    mma_gemm_h<false, false, false><<<gS, blk, SMEM_TOTAL>>>(Qh, Kh, nullptr, S, DIM, SEQ, 0.03125f);

    // softmax rows: S fp32 -> P fp16
    softmax4096<<<SEQ, 256>>>(S, P);

    // out = P @ (VT)^T   [4096,1024] fp32
    dim3 gO(DIM / BN, SEQ / BM);             // (8, 16)
    mma_gemm_h<false, false, false><<<gO, blk, SMEM_TOTAL>>>(P, VTh, nullptr, out, SEQ, DIM, 1.0f);
}

// round 9
// speedup vs baseline: 6.8947x; 1.0312x over previous
#include <cuda_runtime.h>
#include <cuda_fp16.h>
#include <cstdint>
#include <math.h>

#define SEQ 4096
#define DIM 1024

// ---------------- static device scratch (no allocation APIs) ----------------
__device__ __half g_Qh [SEQ * DIM];
__device__ __half g_Kh [SEQ * DIM];
__device__ __half g_VTh[SEQ * DIM];               // V transposed: [DIM][SEQ]
__device__ float  g_S  [(size_t)SEQ * SEQ];       // scores (fp32)
__device__ __half g_P  [(size_t)SEQ * SEQ];       // probs (fp16)
__device__ __half g_Xh [SEQ * DIM];               // fp16-rounded X
__device__ __half g_Wh [3 * DIM * DIM];           // fp16-rounded Wq,Wk,Wv

// ---------------- helpers ----------------
__device__ __forceinline__ uint32_t smem_u32(const void* p) {
    uint32_t a;
    asm("{ .reg .u64 t; cvta.to.shared.u64 t, %1; cvt.u32.u64 %0, t; }" : "=r"(a) : "l"(p));
    return a;
}
#define CP_COMMIT() asm volatile("cp.async.commit_group;" ::: "memory")
#define CP_WAIT(n)  asm volatile("cp.async.wait_group %0;" :: "n"(n) : "memory")

__device__ __forceinline__ void mma_f16(float* d, const uint32_t* a, const uint32_t* b) {
    asm volatile(
        "mma.sync.aligned.m16n8k16.row.col.f32.f16.f16.f32 "
        "{%0,%1,%2,%3}, {%4,%5,%6,%7}, {%8,%9}, {%0,%1,%2,%3};"
        : "+f"(d[0]), "+f"(d[1]), "+f"(d[2]), "+f"(d[3])
        : "r"(a[0]), "r"(a[1]), "r"(a[2]), "r"(a[3]), "r"(b[0]), "r"(b[1]));
}

// ---------------- tile geometry ----------------
static constexpr int BM           = 256;
static constexpr int BN           = 128;
static constexpr int STAGES       = 3;
static constexpr int STRIDE_H     = 72;                     // halves per smem row
static constexpr int STAGE_HALVES = (BM + BN) * STRIDE_H;   // 27648
static constexpr int STAGE_BYTES  = STAGE_HALVES * 2;       // 55296
static constexpr int SMEM_TOTAL   = STAGES * STAGE_BYTES;   // 165888

// ---------------------------------------------------------------------------
// NT GEMM: C[M,N] = alpha * A[M,K] * B[N,K]^T (+ bias), fp16 mma, fp32 accum.
// ---------------------------------------------------------------------------
template <bool HAS_BIAS, bool BIAS_ROW, bool STORE_HALF>
__global__ __launch_bounds__(256, 1)
void mma_gemm_h(const __half* __restrict__ A, const __half* __restrict__ B,
                const float* __restrict__ bias, void* __restrict__ Cv,
                int Kdim, int ldc, float alpha)
{
    extern __shared__ __half sm[];
    const int tid  = threadIdx.x;
    const int lane = tid & 31;
    const int wid  = tid >> 5;
    const int wm   = wid & 3;
    const int wn   = wid >> 2;
    const int lm   = lane >> 2;
    const int lc   = lane & 3;
    const int by   = blockIdx.y * BM;
    const int bx   = blockIdx.x * BN;

    const uint32_t sbase = smem_u32(sm);
    const __half* Abase = A + (size_t)by * Kdim;
    const __half* Bbase = B + (size_t)bx * Kdim;

    float acc[4][8][4];
#pragma unroll
    for (int mt = 0; mt < 4; mt++)
#pragma unroll
        for (int nt = 0; nt < 8; nt++)
#pragma unroll
            for (int q = 0; q < 4; q++) acc[mt][nt][q] = 0.0f;

    const int NK = Kdim >> 6;

    const int ldRow = tid >> 3;
    const int ldC16 = tid & 7;

#define LOAD_STAGE(chunk, stg) do {                                              \
    const int _k0 = (chunk) * 64;                                                \
    const uint32_t _s = sbase + (stg) * STAGE_BYTES;                             \
    _Pragma("unroll")                                                            \
    for (int _i = 0; _i < 8; _i++) {                                             \
        const int _row = _i * 32 + ldRow;                                        \
        const uint32_t _dst = _s + (uint32_t)(_row * STRIDE_H + ldC16 * 8) * 2;  \
        const __half* _g = Abase + (size_t)_row * Kdim + _k0 + ldC16 * 8;        \
        asm volatile("cp.async.cg.shared.global [%0], [%1], 16;"                 \
                     :: "r"(_dst), "l"(_g) : "memory");                          \
    }                                                                            \
    _Pragma("unroll")                                                            \
    for (int _i = 0; _i < 4; _i++) {                                             \
        const int _row = _i * 32 + ldRow;                                        \
        const uint32_t _dst = _s + (uint32_t)((BM + _row) * STRIDE_H + ldC16 * 8) * 2; \
        const __half* _g = Bbase + (size_t)_row * Kdim + _k0 + ldC16 * 8;        \
        asm volatile("cp.async.cg.shared.global [%0], [%1], 16;"                 \
                     :: "r"(_dst), "l"(_g) : "memory");                          \
    }                                                                            \
} while (0)

#pragma unroll
    for (int s = 0; s < STAGES - 1; s++) {
        if (s < NK) LOAD_STAGE(s, s);
        CP_COMMIT();
    }

    for (int c = 0; c < NK; c++) {
        CP_WAIT(STAGES - 2);
        __syncthreads();

        const __half* sA = sm + (c % STAGES) * STAGE_HALVES;
        const __half* sB = sA + BM * STRIDE_H;
        const __half* pA = sA + (wm * 64 + lm) * STRIDE_H + 2 * lc;
        const __half* pB = sB + (wn * 64 + lm) * STRIDE_H + 2 * lc;

#pragma unroll
        for (int ks = 0; ks < 4; ks++) {
            uint32_t afr[4][4], bfr[8][2];
#pragma unroll
            for (int mt = 0; mt < 4; mt++) {
                const __half* p = pA + mt * 16 * STRIDE_H + ks * 16;
                afr[mt][0] = *(const uint32_t*)(p);
                afr[mt][1] = *(const uint32_t*)(p + 8 * STRIDE_H);
                afr[mt][2] = *(const uint32_t*)(p + 8);
                afr[mt][3] = *(const uint32_t*)(p + 8 * STRIDE_H + 8);
            }
#pragma unroll
            for (int nt = 0; nt < 8; nt++) {
                const __half* p = pB + nt * 8 * STRIDE_H + ks * 16;
                bfr[nt][0] = *(const uint32_t*)(p);
                bfr[nt][1] = *(const uint32_t*)(p + 8);
            }
#pragma unroll
            for (int mt = 0; mt < 4; mt++)
#pragma unroll
                for (int nt = 0; nt < 8; nt++)
                    mma_f16(acc[mt][nt], afr[mt], bfr[nt]);
        }

        const int nc = c + STAGES - 1;
        if (nc < NK) LOAD_STAGE(nc, nc % STAGES);
        CP_COMMIT();
    }
#undef LOAD_STAGE

    // ---- epilogue ----
#pragma unroll
    for (int mt = 0; mt < 4; mt++) {
        const int row0 = by + wm * 64 + mt * 16 + lm;
        float brow0 = 0.0f, brow1 = 0.0f;
        if (HAS_BIAS && BIAS_ROW) { brow0 = bias[row0]; brow1 = bias[row0 + 8]; }
#pragma unroll
        for (int nt = 0; nt < 8; nt++) {
            const int col = bx + wn * 64 + nt * 8 + lc * 2;
            float v0 = acc[mt][nt][0] * alpha;
            float v1 = acc[mt][nt][1] * alpha;
            float v2 = acc[mt][nt][2] * alpha;
            float v3 = acc[mt][nt][3] * alpha;
            if (HAS_BIAS) {
                if (BIAS_ROW) { v0 += brow0; v1 += brow0; v2 += brow1; v3 += brow1; }
                else {
                    const float bc0 = bias[col], bc1 = bias[col + 1];
                    v0 += bc0; v1 += bc1; v2 += bc0; v3 += bc1;
                }
            }
            if (STORE_HALF) {
                __half* C = (__half*)Cv;
                *(__half2*)(C + (size_t)row0 * ldc + col)       = __floats2half2_rn(v0, v1);
                *(__half2*)(C + (size_t)(row0 + 8) * ldc + col) = __floats2half2_rn(v2, v3);
            } else {
                float* C = (float*)Cv;
                *(float2*)(C + (size_t)row0 * ldc + col)       = make_float2(v0, v1);
                *(float2*)(C + (size_t)(row0 + 8) * ldc + col) = make_float2(v2, v3);
            }
        }
    }
}

// ---------------------------------------------------------------------------
// Single fused fp32 -> fp16 pre-pass over X, Wq, Wk, Wv (one launch).
// ---------------------------------------------------------------------------
__global__ void f2h_all(const float* __restrict__ X,
                        const float* __restrict__ Wq,
                        const float* __restrict__ Wk,
                        const float* __restrict__ Wv,
                        __half* __restrict__ Xh, __half* __restrict__ Wh)
{
    const int NX = SEQ * DIM;          // 4M
    const int NW = DIM * DIM;          // 1M
    int i = (blockIdx.x * blockDim.x + threadIdx.x) * 4;

    const float* src;
    __half* dst;
    int off;
    if (i < NX)               { src = X;  dst = Xh;          off = i; }
    else if (i < NX + NW)     { src = Wq; dst = Wh;          off = i - NX; }
    else if (i < NX + 2 * NW) { src = Wk; dst = Wh + NW;     off = i - NX - NW; }
    else                      { src = Wv; dst = Wh + 2 * NW; off = i - NX - 2 * NW; }

    float4 v = *(const float4*)(src + off);
    __half2 h0 = __floats2half2_rn(v.x, v.y);
    __half2 h1 = __floats2half2_rn(v.z, v.w);
    uint2 u;
    u.x = *(uint32_t*)&h0;
    u.y = *(uint32_t*)&h1;
    *(uint2*)(dst + off) = u;
}

// ---------------------------------------------------------------------------
// Row softmax: S (fp32) -> P (fp16).
// ---------------------------------------------------------------------------
__global__ void softmax4096(const float* __restrict__ S, __half* __restrict__ P) {
    const int row = blockIdx.x;
    const float4* p = (const float4*)(S + (size_t)row * SEQ);
    __half* pp = P + (size_t)row * SEQ;
    const int t = threadIdx.x;

    float4 v[4];
    float mx = -1e30f;
#pragma unroll
    for (int k = 0; k < 4; k++) {
        v[k] = p[t + 256 * k];
        mx = fmaxf(mx, fmaxf(fmaxf(v[k].x, v[k].y), fmaxf(v[k].z, v[k].w)));
    }
#pragma unroll
    for (int o = 16; o > 0; o >>= 1) mx = fmaxf(mx, __shfl_xor_sync(0xffffffffu, mx, o));

    __shared__ float red[8];
    if ((t & 31) == 0) red[t >> 5] = mx;
    __syncthreads();
    mx = red[0];
#pragma unroll
    for (int i = 1; i < 8; i++) mx = fmaxf(mx, red[i]);

    float sum = 0.0f;
#pragma unroll
    for (int k = 0; k < 4; k++) {
        v[k].x = __expf(v[k].x - mx);
        v[k].y = __expf(v[k].y - mx);
        v[k].z = __expf(v[k].z - mx);
        v[k].w = __expf(v[k].w - mx);
        sum += (v[k].x + v[k].y) + (v[k].z + v[k].w);
    }
#pragma unroll
    for (int o = 16; o > 0; o >>= 1) sum += __shfl_xor_sync(0xffffffffu, sum, o);
    __syncthreads();
    if ((t & 31) == 0) red[t >> 5] = sum;
    __syncthreads();
    float tot = 0.0f;
#pragma unroll
    for (int i = 0; i < 8; i++) tot += red[i];

    const float inv = 1.0f / tot;
#pragma unroll
    for (int k = 0; k < 4; k++) {
        const int e = (t + 256 * k) * 4;
        __half2 h0 = __floats2half2_rn(v[k].x * inv, v[k].y * inv);
        __half2 h1 = __floats2half2_rn(v[k].z * inv, v[k].w * inv);
        uint2 u;
        u.x = *(uint32_t*)&h0;
        u.y = *(uint32_t*)&h1;
        *(uint2*)(pp + e) = u;
    }
}

// ---------------------------------------------------------------------------
extern "C" void kernel_launch(void* const* d_in, const int* in_sizes, int n_in,
                              void* d_out, int out_size)
{
    const float* X  = (const float*)d_in[0];
    const float* Wq = (const float*)d_in[1];
    const float* bq = (const float*)d_in[2];
    const float* Wk = (const float*)d_in[3];
    const float* bk = (const float*)d_in[4];
    const float* Wv = (const float*)d_in[5];
    const float* bv = (const float*)d_in[6];
    float* out = (float*)d_out;

    __half *Qh, *Kh, *VTh, *P, *Xh, *Wh;
    float *S;
    cudaGetSymbolAddress((void**)&Qh,  g_Qh);
    cudaGetSymbolAddress((void**)&Kh,  g_Kh);
    cudaGetSymbolAddress((void**)&VTh, g_VTh);
    cudaGetSymbolAddress((void**)&S,   g_S);
    cudaGetSymbolAddress((void**)&P,   g_P);
    cudaGetSymbolAddress((void**)&Xh,  g_Xh);
    cudaGetSymbolAddress((void**)&Wh,  g_Wh);
    __half* Wqh = Wh;
    __half* Wkh = Wh + (size_t)DIM * DIM;
    __half* Wvh = Wh + (size_t)2 * DIM * DIM;

    cudaFuncSetAttribute(mma_gemm_h<true,  false, true >, cudaFuncAttributeMaxDynamicSharedMemorySize, SMEM_TOTAL);
    cudaFuncSetAttribute(mma_gemm_h<true,  true,  true >, cudaFuncAttributeMaxDynamicSharedMemorySize, SMEM_TOTAL);
    cudaFuncSetAttribute(mma_gemm_h<false, false, false>, cudaFuncAttributeMaxDynamicSharedMemorySize, SMEM_TOTAL);

    // one-time side stream + events (first call is the uncaptured correctness
    // run; captured calls take the already-initialized path — identical work).
    static cudaStream_t s1 = nullptr;
    static cudaEvent_t evS = nullptr, evV = nullptr;
    if (!s1) {
        cudaStreamCreateWithFlags(&s1, cudaStreamNonBlocking);
        cudaEventCreateWithFlags(&evS, cudaEventDisableTiming);
        cudaEventCreateWithFlags(&evV, cudaEventDisableTiming);
    }

    dim3 blk(256);
    dim3 gQK(DIM / BN, SEQ / BM);            // (8, 16)
    dim3 gVT(SEQ / BN, DIM / BM);            // (32, 4)
    dim3 gS(SEQ / BN, SEQ / BM);             // (32, 16)
    dim3 gO(DIM / BN, SEQ / BM);             // (8, 16)

    // fused fp32->fp16 of all operands (one launch)
    f2h_all<<<(SEQ * DIM + 3 * DIM * DIM) / 1024, 256>>>(X, Wq, Wk, Wv, Xh, Wh);

    // Q, K projections (main stream)
    mma_gemm_h<true, false, true ><<<gQK, blk, SMEM_TOTAL>>>(Xh, Wqh, bq, Qh, DIM, DIM, 1.0f);
    mma_gemm_h<true, false, true ><<<gQK, blk, SMEM_TOTAL>>>(Xh, Wkh, bk, Kh, DIM, DIM, 1.0f);

    // S = (Q @ K^T) / 32
    mma_gemm_h<false, false, false><<<gS, blk, SMEM_TOTAL>>>(Qh, Kh, nullptr, S, DIM, SEQ, 0.03125f);

    // fork: VT projection on side stream, concurrent with softmax
    cudaEventRecord(evS, 0);
    cudaStreamWaitEvent(s1, evS, 0);
    mma_gemm_h<true, true, true ><<<gVT, blk, SMEM_TOTAL, s1>>>(Wvh, Xh, bv, VTh, DIM, SEQ, 1.0f);
    cudaEventRecord(evV, s1);

    softmax4096<<<SEQ, 256>>>(S, P);         // main stream

    // join, then PV
    cudaStreamWaitEvent(0, evV, 0);
    mma_gemm_h<false, false, false><<<gO, blk, SMEM_TOTAL>>>(P, VTh, nullptr, out, SEQ, DIM, 1.0f);
}

// round 10
// speedup vs baseline: 7.1117x; 1.0315x over previous
#include <cuda_runtime.h>
#include <cuda_fp16.h>
#include <cstdint>
#include <math.h>

#define SEQ 4096
#define DIM 1024

// ---------------- static device scratch (no allocation APIs) ----------------
__device__ __half g_Qh [SEQ * DIM];
__device__ __half g_Kh [SEQ * DIM];
__device__ __half g_VTh[SEQ * DIM];               // V transposed: [DIM][SEQ]
__device__ float  g_S  [(size_t)SEQ * SEQ];       // scores (fp32)
__device__ __half g_P  [(size_t)SEQ * SEQ];       // probs (fp16)
__device__ __half g_Xh [SEQ * DIM];               // fp16-rounded X
__device__ __half g_Wh [3 * DIM * DIM];           // fp16-rounded Wq,Wk,Wv

// ---------------- helpers ----------------
__device__ __forceinline__ uint32_t smem_u32(const void* p) {
    uint32_t a;
    asm("{ .reg .u64 t; cvta.to.shared.u64 t, %1; cvt.u32.u64 %0, t; }" : "=r"(a) : "l"(p));
    return a;
}
#define CP_COMMIT() asm volatile("cp.async.commit_group;" ::: "memory")
#define CP_WAIT(n)  asm volatile("cp.async.wait_group %0;" :: "n"(n) : "memory")

__device__ __forceinline__ void mma_f16(float* d, const uint32_t* a, const uint32_t* b) {
    asm volatile(
        "mma.sync.aligned.m16n8k16.row.col.f32.f16.f16.f32 "
        "{%0,%1,%2,%3}, {%4,%5,%6,%7}, {%8,%9}, {%0,%1,%2,%3};"
        : "+f"(d[0]), "+f"(d[1]), "+f"(d[2]), "+f"(d[3])
        : "r"(a[0]), "r"(a[1]), "r"(a[2]), "r"(a[3]), "r"(b[0]), "r"(b[1]));
}

// ---------------- tile geometry ----------------
// Block 128x128, BK=64 halves. 8 warps (2m x 4n), warp tile 64x32.
// 2 CTAs/SM (smem 110592 x2, regs capped at 128/thread).
static constexpr int BM           = 128;
static constexpr int BN           = 128;
static constexpr int STAGES       = 3;
static constexpr int STRIDE_H     = 72;                     // halves per smem row
static constexpr int STAGE_HALVES = (BM + BN) * STRIDE_H;   // 18432
static constexpr int STAGE_BYTES  = STAGE_HALVES * 2;       // 36864
static constexpr int SMEM_TOTAL   = STAGES * STAGE_BYTES;   // 110592

// ---------------------------------------------------------------------------
// NT GEMM: C[M,N] = alpha * A[M,K] * B[N,K]^T (+ bias), fp16 mma, fp32 accum.
// A,B half, K-major. Grid: (N/BN, M/BM), 256 threads, 2 CTAs/SM.
// ---------------------------------------------------------------------------
template <bool HAS_BIAS, bool BIAS_ROW, bool STORE_HALF>
__global__ __launch_bounds__(256, 2)
void mma_gemm_h(const __half* __restrict__ A, const __half* __restrict__ B,
                const float* __restrict__ bias, void* __restrict__ Cv,
                int Kdim, int ldc, float alpha)
{
    extern __shared__ __half sm[];
    const int tid  = threadIdx.x;
    const int lane = tid & 31;
    const int wid  = tid >> 5;
    const int wm   = wid & 1;          // warp m: 0..1 (64 rows each)
    const int wn   = wid >> 1;         // warp n: 0..3 (32 cols each)
    const int lm   = lane >> 2;        // 0..7
    const int lc   = lane & 3;         // 0..3
    const int by   = blockIdx.y * BM;
    const int bx   = blockIdx.x * BN;

    const uint32_t sbase = smem_u32(sm);
    const __half* Abase = A + (size_t)by * Kdim;
    const __half* Bbase = B + (size_t)bx * Kdim;

    float acc[4][4][4];                // 4 mt x 4 nt x 4 = 64 regs
#pragma unroll
    for (int mt = 0; mt < 4; mt++)
#pragma unroll
        for (int nt = 0; nt < 4; nt++)
#pragma unroll
            for (int q = 0; q < 4; q++) acc[mt][nt][q] = 0.0f;

    const int NK = Kdim >> 6;          // K chunks of 64 halves

    // cp.async: 16B per op. A: 128 rows x 8 (4 iters), B: 128 rows x 8 (4 iters).
    const int ldRow = tid >> 3;        // 0..31
    const int ldC16 = tid & 7;         // 0..7

#define LOAD_STAGE(chunk, stg) do {                                              \
    const int _k0 = (chunk) * 64;                                                \
    const uint32_t _s = sbase + (stg) * STAGE_BYTES;                             \
    _Pragma("unroll")                                                            \
    for (int _i = 0; _i < 4; _i++) {                                             \
        const int _row = _i * 32 + ldRow;                                        \
        const uint32_t _dst = _s + (uint32_t)(_row * STRIDE_H + ldC16 * 8) * 2;  \
        const __half* _g = Abase + (size_t)_row * Kdim + _k0 + ldC16 * 8;        \
        asm volatile("cp.async.cg.shared.global [%0], [%1], 16;"                 \
                     :: "r"(_dst), "l"(_g) : "memory");                          \
    }                                                                            \
    _Pragma("unroll")                                                            \
    for (int _i = 0; _i < 4; _i++) {                                             \
        const int _row = _i * 32 + ldRow;                                        \
        const uint32_t _dst = _s + (uint32_t)((BM + _row) * STRIDE_H + ldC16 * 8) * 2; \
        const __half* _g = Bbase + (size_t)_row * Kdim + _k0 + ldC16 * 8;        \
        asm volatile("cp.async.cg.shared.global [%0], [%1], 16;"                 \
                     :: "r"(_dst), "l"(_g) : "memory");                          \
    }                                                                            \
} while (0)

#pragma unroll
    for (int s = 0; s < STAGES - 1; s++) {
        if (s < NK) LOAD_STAGE(s, s);
        CP_COMMIT();
    }

    for (int c = 0; c < NK; c++) {
        CP_WAIT(STAGES - 2);
        __syncthreads();               // chunk c resident; stage (c-1)%S free

        const __half* sA = sm + (c % STAGES) * STAGE_HALVES;
        const __half* sB = sA + BM * STRIDE_H;
        const __half* pA = sA + (wm * 64 + lm) * STRIDE_H + 2 * lc;
        const __half* pB = sB + (wn * 32 + lm) * STRIDE_H + 2 * lc;

#pragma unroll
        for (int ks = 0; ks < 4; ks++) {       // 4 x k16 slices
            uint32_t afr[4][4], bfr[4][2];
#pragma unroll
            for (int mt = 0; mt < 4; mt++) {
                const __half* p = pA + mt * 16 * STRIDE_H + ks * 16;
                afr[mt][0] = *(const uint32_t*)(p);
                afr[mt][1] = *(const uint32_t*)(p + 8 * STRIDE_H);
                afr[mt][2] = *(const uint32_t*)(p + 8);
                afr[mt][3] = *(const uint32_t*)(p + 8 * STRIDE_H + 8);
            }
#pragma unroll
            for (int nt = 0; nt < 4; nt++) {
                const __half* p = pB + nt * 8 * STRIDE_H + ks * 16;
                bfr[nt][0] = *(const uint32_t*)(p);
                bfr[nt][1] = *(const uint32_t*)(p + 8);
            }
#pragma unroll
            for (int mt = 0; mt < 4; mt++)
#pragma unroll
                for (int nt = 0; nt < 4; nt++)
                    mma_f16(acc[mt][nt], afr[mt], bfr[nt]);
        }

        const int nc = c + STAGES - 1;
        if (nc < NK) LOAD_STAGE(nc, nc % STAGES);
        CP_COMMIT();
    }
#undef LOAD_STAGE

    // ---- epilogue ----
#pragma unroll
    for (int mt = 0; mt < 4; mt++) {
        const int row0 = by + wm * 64 + mt * 16 + lm;   // and row0+8
        float brow0 = 0.0f, brow1 = 0.0f;
        if (HAS_BIAS && BIAS_ROW) { brow0 = bias[row0]; brow1 = bias[row0 + 8]; }
#pragma unroll
        for (int nt = 0; nt < 4; nt++) {
            const int col = bx + wn * 32 + nt * 8 + lc * 2;
            float v0 = acc[mt][nt][0] * alpha;
            float v1 = acc[mt][nt][1] * alpha;
            float v2 = acc[mt][nt][2] * alpha;
            float v3 = acc[mt][nt][3] * alpha;
            if (HAS_BIAS) {
                if (BIAS_ROW) { v0 += brow0; v1 += brow0; v2 += brow1; v3 += brow1; }
                else {
                    const float bc0 = bias[col], bc1 = bias[col + 1];
                    v0 += bc0; v1 += bc1; v2 += bc0; v3 += bc1;
                }
            }
            if (STORE_HALF) {
                __half* C = (__half*)Cv;
                *(__half2*)(C + (size_t)row0 * ldc + col)       = __floats2half2_rn(v0, v1);
                *(__half2*)(C + (size_t)(row0 + 8) * ldc + col) = __floats2half2_rn(v2, v3);
            } else {
                float* C = (float*)Cv;
                *(float2*)(C + (size_t)row0 * ldc + col)       = make_float2(v0, v1);
                *(float2*)(C + (size_t)(row0 + 8) * ldc + col) = make_float2(v2, v3);
            }
        }
    }
}

// ---------------------------------------------------------------------------
// Single fused fp32 -> fp16 pre-pass over X, Wq, Wk, Wv (one launch).
// ---------------------------------------------------------------------------
__global__ void f2h_all(const float* __restrict__ X,
                        const float* __restrict__ Wq,
                        const float* __restrict__ Wk,
                        const float* __restrict__ Wv,
                        __half* __restrict__ Xh, __half* __restrict__ Wh)
{
    const int NX = SEQ * DIM;
    const int NW = DIM * DIM;
    int i = (blockIdx.x * blockDim.x + threadIdx.x) * 4;

    const float* src;
    __half* dst;
    int off;
    if (i < NX)               { src = X;  dst = Xh;          off = i; }
    else if (i < NX + NW)     { src = Wq; dst = Wh;          off = i - NX; }
    else if (i < NX + 2 * NW) { src = Wk; dst = Wh + NW;     off = i - NX - NW; }
    else                      { src = Wv; dst = Wh + 2 * NW; off = i - NX - 2 * NW; }

    float4 v = *(const float4*)(src + off);
    __half2 h0 = __floats2half2_rn(v.x, v.y);
    __half2 h1 = __floats2half2_rn(v.z, v.w);
    uint2 u;
    u.x = *(uint32_t*)&h0;
    u.y = *(uint32_t*)&h1;
    *(uint2*)(dst + off) = u;
}

// ---------------------------------------------------------------------------
// Row softmax: S (fp32) -> P (fp16).
// ---------------------------------------------------------------------------
__global__ void softmax4096(const float* __restrict__ S, __half* __restrict__ P) {
    const int row = blockIdx.x;
    const float4* p = (const float4*)(S + (size_t)row * SEQ);
    __half* pp = P + (size_t)row * SEQ;
    const int t = threadIdx.x;

    float4 v[4];
    float mx = -1e30f;
#pragma unroll
    for (int k = 0; k < 4; k++) {
        v[k] = p[t + 256 * k];
        mx = fmaxf(mx, fmaxf(fmaxf(v[k].x, v[k].y), fmaxf(v[k].z, v[k].w)));
    }
#pragma unroll
    for (int o = 16; o > 0; o >>= 1) mx = fmaxf(mx, __shfl_xor_sync(0xffffffffu, mx, o));

    __shared__ float red[8];
    if ((t & 31) == 0) red[t >> 5] = mx;
    __syncthreads();
    mx = red[0];
#pragma unroll
    for (int i = 1; i < 8; i++) mx = fmaxf(mx, red[i]);

    float sum = 0.0f;
#pragma unroll
    for (int k = 0; k < 4; k++) {
        v[k].x = __expf(v[k].x - mx);
        v[k].y = __expf(v[k].y - mx);
        v[k].z = __expf(v[k].z - mx);
        v[k].w = __expf(v[k].w - mx);
        sum += (v[k].x + v[k].y) + (v[k].z + v[k].w);
    }
#pragma unroll
    for (int o = 16; o > 0; o >>= 1) sum += __shfl_xor_sync(0xffffffffu, sum, o);
    __syncthreads();
    if ((t & 31) == 0) red[t >> 5] = sum;
    __syncthreads();
    float tot = 0.0f;
#pragma unroll
    for (int i = 0; i < 8; i++) tot += red[i];

    const float inv = 1.0f / tot;
#pragma unroll
    for (int k = 0; k < 4; k++) {
        const int e = (t + 256 * k) * 4;
        __half2 h0 = __floats2half2_rn(v[k].x * inv, v[k].y * inv);
        __half2 h1 = __floats2half2_rn(v[k].z * inv, v[k].w * inv);
        uint2 u;
        u.x = *(uint32_t*)&h0;
        u.y = *(uint32_t*)&h1;
        *(uint2*)(pp + e) = u;
    }
}

// ---------------------------------------------------------------------------
extern "C" void kernel_launch(void* const* d_in, const int* in_sizes, int n_in,
                              void* d_out, int out_size)
{
    const float* X  = (const float*)d_in[0];
    const float* Wq = (const float*)d_in[1];
    const float* bq = (const float*)d_in[2];
    const float* Wk = (const float*)d_in[3];
    const float* bk = (const float*)d_in[4];
    const float* Wv = (const float*)d_in[5];
    const float* bv = (const float*)d_in[6];
    float* out = (float*)d_out;

    __half *Qh, *Kh, *VTh, *P, *Xh, *Wh;
    float *S;
    cudaGetSymbolAddress((void**)&Qh,  g_Qh);
    cudaGetSymbolAddress((void**)&Kh,  g_Kh);
    cudaGetSymbolAddress((void**)&VTh, g_VTh);
    cudaGetSymbolAddress((void**)&S,   g_S);
    cudaGetSymbolAddress((void**)&P,   g_P);
    cudaGetSymbolAddress((void**)&Xh,  g_Xh);
    cudaGetSymbolAddress((void**)&Wh,  g_Wh);
    __half* Wqh = Wh;
    __half* Wkh = Wh + (size_t)DIM * DIM;
    __half* Wvh = Wh + (size_t)2 * DIM * DIM;

    cudaFuncSetAttribute(mma_gemm_h<true,  false, true >, cudaFuncAttributeMaxDynamicSharedMemorySize, SMEM_TOTAL);
    cudaFuncSetAttribute(mma_gemm_h<true,  true,  true >, cudaFuncAttributeMaxDynamicSharedMemorySize, SMEM_TOTAL);
    cudaFuncSetAttribute(mma_gemm_h<false, false, false>, cudaFuncAttributeMaxDynamicSharedMemorySize, SMEM_TOTAL);

    static cudaStream_t s1 = nullptr;
    static cudaEvent_t evS = nullptr, evV = nullptr;
    if (!s1) {
        cudaStreamCreateWithFlags(&s1, cudaStreamNonBlocking);
        cudaEventCreateWithFlags(&evS, cudaEventDisableTiming);
        cudaEventCreateWithFlags(&evV, cudaEventDisableTiming);
    }

    dim3 blk(256);
    dim3 gQK(DIM / BN, SEQ / BM);            // (8, 32)
    dim3 gVT(SEQ / BN, DIM / BM);            // (32, 8)
    dim3 gS(SEQ / BN, SEQ / BM);             // (32, 32)
    dim3 gO(DIM / BN, SEQ / BM);             // (8, 32)

    // fused fp32->fp16 of all operands (one launch)
    f2h_all<<<(SEQ * DIM + 3 * DIM * DIM) / 1024, 256>>>(X, Wq, Wk, Wv, Xh, Wh);

    // Q, K projections (main stream)
    mma_gemm_h<true, false, true ><<<gQK, blk, SMEM_TOTAL>>>(Xh, Wqh, bq, Qh, DIM, DIM, 1.0f);
    mma_gemm_h<true, false, true ><<<gQK, blk, SMEM_TOTAL>>>(Xh, Wkh, bk, Kh, DIM, DIM, 1.0f);

    // S = (Q @ K^T) / 32
    mma_gemm_h<false, false, false><<<gS, blk, SMEM_TOTAL>>>(Qh, Kh, nullptr, S, DIM, SEQ, 0.03125f);

    // fork: VT projection on side stream, concurrent with softmax
    cudaEventRecord(evS, 0);
    cudaStreamWaitEvent(s1, evS, 0);
    mma_gemm_h<true, true, true ><<<gVT, blk, SMEM_TOTAL, s1>>>(Wvh, Xh, bv, VTh, DIM, SEQ, 1.0f);
    cudaEventRecord(evV, s1);

    softmax4096<<<SEQ, 256>>>(S, P);         // main stream

    // join, then PV
    cudaStreamWaitEvent(0, evV, 0);
    mma_gemm_h<false, false, false><<<gO, blk, SMEM_TOTAL>>>(P, VTh, nullptr, out, SEQ, DIM, 1.0f);
}

// round 11
// speedup vs baseline: 7.5125x; 1.0563x over previous
#include <cuda_runtime.h>
#include <cuda_fp16.h>
#include <cstdint>
#include <math.h>

#define SEQ 4096
#define DIM 1024

// ---------------- static device scratch (no allocation APIs) ----------------
__device__ __half g_Qh [SEQ * DIM];
__device__ __half g_Kh [SEQ * DIM];
__device__ __half g_VTh[SEQ * DIM];               // V transposed: [DIM][SEQ]
__device__ float  g_S  [(size_t)SEQ * SEQ];       // scores (fp32)
__device__ __half g_P  [(size_t)SEQ * SEQ];       // probs (fp16)
__device__ __half g_Xh [SEQ * DIM];               // fp16-rounded X
__device__ __half g_Wh [3 * DIM * DIM];           // fp16-rounded Wq,Wk,Wv

// ---------------- helpers ----------------
__device__ __forceinline__ uint32_t smem_u32(const void* p) {
    uint32_t a;
    asm("{ .reg .u64 t; cvta.to.shared.u64 t, %1; cvt.u32.u64 %0, t; }" : "=r"(a) : "l"(p));
    return a;
}
#define CP_COMMIT() asm volatile("cp.async.commit_group;" ::: "memory")
#define CP_WAIT(n)  asm volatile("cp.async.wait_group %0;" :: "n"(n) : "memory")

__device__ __forceinline__ void mma_f16(float* d, const uint32_t* a, const uint32_t* b) {
    asm volatile(
        "mma.sync.aligned.m16n8k16.row.col.f32.f16.f16.f32 "
        "{%0,%1,%2,%3}, {%4,%5,%6,%7}, {%8,%9}, {%0,%1,%2,%3};"
        : "+f"(d[0]), "+f"(d[1]), "+f"(d[2]), "+f"(d[3])
        : "r"(a[0]), "r"(a[1]), "r"(a[2]), "r"(a[3]), "r"(b[0]), "r"(b[1]));
}

#define LDSM_X4(r0, r1, r2, r3, addr) \
    asm volatile("ldmatrix.sync.aligned.m8n8.x4.shared.b16 {%0,%1,%2,%3}, [%4];" \
                 : "=r"(r0), "=r"(r1), "=r"(r2), "=r"(r3) : "r"(addr))

// ---------------- tile geometry ----------------
// Block 128x128, BK=64 halves. 8 warps (2m x 4n), warp tile 64x32. 2 CTAs/SM.
static constexpr int BM           = 128;
static constexpr int BN           = 128;
static constexpr int STAGES       = 3;
static constexpr int STRIDE_H     = 72;                     // halves per smem row
static constexpr int STAGE_HALVES = (BM + BN) * STRIDE_H;   // 18432
static constexpr int STAGE_BYTES  = STAGE_HALVES * 2;       // 36864
static constexpr int SMEM_TOTAL   = STAGES * STAGE_BYTES;   // 110592

// ---------------------------------------------------------------------------
// NT GEMM: C[M,N] = alpha * A[M,K] * B[N,K]^T (+ bias), fp16 mma, fp32 accum.
// ldmatrix fragment loads. Grid: (N/BN, M/BM), 256 threads, 2 CTAs/SM.
// ---------------------------------------------------------------------------
template <bool HAS_BIAS, bool BIAS_ROW, bool STORE_HALF>
__global__ __launch_bounds__(256, 2)
void mma_gemm_h(const __half* __restrict__ A, const __half* __restrict__ B,
                const float* __restrict__ bias, void* __restrict__ Cv,
                int Kdim, int ldc, float alpha)
{
    extern __shared__ __half sm[];
    const int tid  = threadIdx.x;
    const int lane = tid & 31;
    const int wid  = tid >> 5;
    const int wm   = wid & 1;          // warp m: 0..1 (64 rows each)
    const int wn   = wid >> 1;         // warp n: 0..3 (32 cols each)
    const int lm   = lane >> 2;        // 0..7
    const int lc   = lane & 3;         // 0..3
    const int by   = blockIdx.y * BM;
    const int bx   = blockIdx.x * BN;

    const uint32_t sbase = smem_u32(sm);
    const __half* Abase = A + (size_t)by * Kdim;
    const __half* Bbase = B + (size_t)bx * Kdim;

    // per-lane ldmatrix base offsets (halves), relative to stage start
    // A x4: lanes 0-15 -> rows (lane&15), k+0; lanes 16-31 -> rows (lane&15), k+8
    const uint32_t aOff = (uint32_t)(((wm * 64 + (lane & 15)) * STRIDE_H
                                      + (lane >> 4) * 8) * 2);
    // B x4: quads -> (n, k): (0..7,k0),(0..7,k8),(8..15,k0),(8..15,k8)
    const uint32_t bOff = (uint32_t)(((BM + wn * 32 + ((lane >> 4) & 1) * 8 + (lane & 7)) * STRIDE_H
                                      + ((lane >> 3) & 1) * 8) * 2);

    float acc[4][4][4];                // 4 mt x 4 nt x 4 = 64 regs
#pragma unroll
    for (int mt = 0; mt < 4; mt++)
#pragma unroll
        for (int nt = 0; nt < 4; nt++)
#pragma unroll
            for (int q = 0; q < 4; q++) acc[mt][nt][q] = 0.0f;

    const int NK = Kdim >> 6;          // K chunks of 64 halves

    const int ldRow = tid >> 3;        // 0..31
    const int ldC16 = tid & 7;         // 0..7

#define LOAD_STAGE(chunk, stg) do {                                              \
    const int _k0 = (chunk) * 64;                                                \
    const uint32_t _s = sbase + (stg) * STAGE_BYTES;                             \
    _Pragma("unroll")                                                            \
    for (int _i = 0; _i < 4; _i++) {                                             \
        const int _row = _i * 32 + ldRow;                                        \
        const uint32_t _dst = _s + (uint32_t)(_row * STRIDE_H + ldC16 * 8) * 2;  \
        const __half* _g = Abase + (size_t)_row * Kdim + _k0 + ldC16 * 8;        \
        asm volatile("cp.async.cg.shared.global [%0], [%1], 16;"                 \
                     :: "r"(_dst), "l"(_g) : "memory");                          \
    }                                                                            \
    _Pragma("unroll")                                                            \
    for (int _i = 0; _i < 4; _i++) {                                             \
        const int _row = _i * 32 + ldRow;                                        \
        const uint32_t _dst = _s + (uint32_t)((BM + _row) * STRIDE_H + ldC16 * 8) * 2; \
        const __half* _g = Bbase + (size_t)_row * Kdim + _k0 + ldC16 * 8;        \
        asm volatile("cp.async.cg.shared.global [%0], [%1], 16;"                 \
                     :: "r"(_dst), "l"(_g) : "memory");                          \
    }                                                                            \
} while (0)

#pragma unroll
    for (int s = 0; s < STAGES - 1; s++) {
        if (s < NK) LOAD_STAGE(s, s);
        CP_COMMIT();
    }

    for (int c = 0; c < NK; c++) {
        CP_WAIT(STAGES - 2);
        __syncthreads();               // chunk c resident; stage (c-1)%S free

        const uint32_t sstage = sbase + (c % STAGES) * STAGE_BYTES;
        const uint32_t aAddr = sstage + aOff;
        const uint32_t bAddr = sstage + bOff;

#pragma unroll
        for (int ks = 0; ks < 4; ks++) {       // 4 x k16 slices
            uint32_t afr[4][4], bfr[4][2];
#pragma unroll
            for (int mt = 0; mt < 4; mt++)
                LDSM_X4(afr[mt][0], afr[mt][1], afr[mt][2], afr[mt][3],
                        aAddr + (uint32_t)(mt * 16 * STRIDE_H * 2 + ks * 32));
#pragma unroll
            for (int nt2 = 0; nt2 < 2; nt2++)
                LDSM_X4(bfr[2 * nt2][0], bfr[2 * nt2][1],
                        bfr[2 * nt2 + 1][0], bfr[2 * nt2 + 1][1],
                        bAddr + (uint32_t)(nt2 * 16 * STRIDE_H * 2 + ks * 32));
#pragma unroll
            for (int mt = 0; mt < 4; mt++)
#pragma unroll
                for (int nt = 0; nt < 4; nt++)
                    mma_f16(acc[mt][nt], afr[mt], bfr[nt]);
        }

        const int nc = c + STAGES - 1;
        if (nc < NK) LOAD_STAGE(nc, nc % STAGES);
        CP_COMMIT();
    }
#undef LOAD_STAGE

    // ---- epilogue ----
#pragma unroll
    for (int mt = 0; mt < 4; mt++) {
        const int row0 = by + wm * 64 + mt * 16 + lm;   // and row0+8
        float brow0 = 0.0f, brow1 = 0.0f;
        if (HAS_BIAS && BIAS_ROW) { brow0 = bias[row0]; brow1 = bias[row0 + 8]; }
#pragma unroll
        for (int nt = 0; nt < 4; nt++) {
            const int col = bx + wn * 32 + nt * 8 + lc * 2;
            float v0 = acc[mt][nt][0] * alpha;
            float v1 = acc[mt][nt][1] * alpha;
            float v2 = acc[mt][nt][2] * alpha;
            float v3 = acc[mt][nt][3] * alpha;
            if (HAS_BIAS) {
                if (BIAS_ROW) { v0 += brow0; v1 += brow0; v2 += brow1; v3 += brow1; }
                else {
                    const float bc0 = bias[col], bc1 = bias[col + 1];
                    v0 += bc0; v1 += bc1; v2 += bc0; v3 += bc1;
                }
            }
            if (STORE_HALF) {
                __half* C = (__half*)Cv;
                *(__half2*)(C + (size_t)row0 * ldc + col)       = __floats2half2_rn(v0, v1);
                *(__half2*)(C + (size_t)(row0 + 8) * ldc + col) = __floats2half2_rn(v2, v3);
            } else {
                float* C = (float*)Cv;
                *(float2*)(C + (size_t)row0 * ldc + col)       = make_float2(v0, v1);
                *(float2*)(C + (size_t)(row0 + 8) * ldc + col) = make_float2(v2, v3);
            }
        }
    }
}

// ---------------------------------------------------------------------------
// Single fused fp32 -> fp16 pre-pass over X, Wq, Wk, Wv (one launch).
// ---------------------------------------------------------------------------
__global__ void f2h_all(const float* __restrict__ X,
                        const float* __restrict__ Wq,
                        const float* __restrict__ Wk,
                        const float* __restrict__ Wv,
                        __half* __restrict__ Xh, __half* __restrict__ Wh)
{
    const int NX = SEQ * DIM;
    const int NW = DIM * DIM;
    int i = (blockIdx.x * blockDim.x + threadIdx.x) * 4;

    const float* src;
    __half* dst;
    int off;
    if (i < NX)               { src = X;  dst = Xh;          off = i; }
    else if (i < NX + NW)     { src = Wq; dst = Wh;          off = i - NX; }
    else if (i < NX + 2 * NW) { src = Wk; dst = Wh + NW;     off = i - NX - NW; }
    else                      { src = Wv; dst = Wh + 2 * NW; off = i - NX - 2 * NW; }

    float4 v = *(const float4*)(src + off);
    __half2 h0 = __floats2half2_rn(v.x, v.y);
    __half2 h1 = __floats2half2_rn(v.z, v.w);
    uint2 u;
    u.x = *(uint32_t*)&h0;
    u.y = *(uint32_t*)&h1;
    *(uint2*)(dst + off) = u;
}

// ---------------------------------------------------------------------------
// Row softmax: S (fp32) -> P (fp16).
// ---------------------------------------------------------------------------
__global__ void softmax4096(const float* __restrict__ S, __half* __restrict__ P) {
    const int row = blockIdx.x;
    const float4* p = (const float4*)(S + (size_t)row * SEQ);
    __half* pp = P + (size_t)row * SEQ;
    const int t = threadIdx.x;

    float4 v[4];
    float mx = -1e30f;
#pragma unroll
    for (int k = 0; k < 4; k++) {
        v[k] = p[t + 256 * k];
        mx = fmaxf(mx, fmaxf(fmaxf(v[k].x, v[k].y), fmaxf(v[k].z, v[k].w)));
    }
#pragma unroll
    for (int o = 16; o > 0; o >>= 1) mx = fmaxf(mx, __shfl_xor_sync(0xffffffffu, mx, o));

    __shared__ float red[8];
    if ((t & 31) == 0) red[t >> 5] = mx;
    __syncthreads();
    mx = red[0];
#pragma unroll
    for (int i = 1; i < 8; i++) mx = fmaxf(mx, red[i]);

    float sum = 0.0f;
#pragma unroll
    for (int k = 0; k < 4; k++) {
        v[k].x = __expf(v[k].x - mx);
        v[k].y = __expf(v[k].y - mx);
        v[k].z = __expf(v[k].z - mx);
        v[k].w = __expf(v[k].w - mx);
        sum += (v[k].x + v[k].y) + (v[k].z + v[k].w);
    }
#pragma unroll
    for (int o = 16; o > 0; o >>= 1) sum += __shfl_xor_sync(0xffffffffu, sum, o);
    __syncthreads();
    if ((t & 31) == 0) red[t >> 5] = sum;
    __syncthreads();
    float tot = 0.0f;
#pragma unroll
    for (int i = 0; i < 8; i++) tot += red[i];

    const float inv = 1.0f / tot;
#pragma unroll
    for (int k = 0; k < 4; k++) {
        const int e = (t + 256 * k) * 4;
        __half2 h0 = __floats2half2_rn(v[k].x * inv, v[k].y * inv);
        __half2 h1 = __floats2half2_rn(v[k].z * inv, v[k].w * inv);
        uint2 u;
        u.x = *(uint32_t*)&h0;
        u.y = *(uint32_t*)&h1;
        *(uint2*)(pp + e) = u;
    }
}

// ---------------------------------------------------------------------------
extern "C" void kernel_launch(void* const* d_in, const int* in_sizes, int n_in,
                              void* d_out, int out_size)
{
    const float* X  = (const float*)d_in[0];
    const float* Wq = (const float*)d_in[1];
    const float* bq = (const float*)d_in[2];
    const float* Wk = (const float*)d_in[3];
    const float* bk = (const float*)d_in[4];
    const float* Wv = (const float*)d_in[5];
    const float* bv = (const float*)d_in[6];
    float* out = (float*)d_out;

    __half *Qh, *Kh, *VTh, *P, *Xh, *Wh;
    float *S;
    cudaGetSymbolAddress((void**)&Qh,  g_Qh);
    cudaGetSymbolAddress((void**)&Kh,  g_Kh);
    cudaGetSymbolAddress((void**)&VTh, g_VTh);
    cudaGetSymbolAddress((void**)&S,   g_S);
    cudaGetSymbolAddress((void**)&P,   g_P);
    cudaGetSymbolAddress((void**)&Xh,  g_Xh);
    cudaGetSymbolAddress((void**)&Wh,  g_Wh);
    __half* Wqh = Wh;
    __half* Wkh = Wh + (size_t)DIM * DIM;
    __half* Wvh = Wh + (size_t)2 * DIM * DIM;

    cudaFuncSetAttribute(mma_gemm_h<true,  false, true >, cudaFuncAttributeMaxDynamicSharedMemorySize, SMEM_TOTAL);
    cudaFuncSetAttribute(mma_gemm_h<true,  true,  true >, cudaFuncAttributeMaxDynamicSharedMemorySize, SMEM_TOTAL);
    cudaFuncSetAttribute(mma_gemm_h<false, false, false>, cudaFuncAttributeMaxDynamicSharedMemorySize, SMEM_TOTAL);

    static cudaStream_t s1 = nullptr;
    static cudaEvent_t evS = nullptr, evV = nullptr;
    if (!s1) {
        cudaStreamCreateWithFlags(&s1, cudaStreamNonBlocking);
        cudaEventCreateWithFlags(&evS, cudaEventDisableTiming);
        cudaEventCreateWithFlags(&evV, cudaEventDisableTiming);
    }

    dim3 blk(256);
    dim3 gQK(DIM / BN, SEQ / BM);            // (8, 32)
    dim3 gVT(SEQ / BN, DIM / BM);            // (32, 8)
    dim3 gS(SEQ / BN, SEQ / BM);             // (32, 32)
    dim3 gO(DIM / BN, SEQ / BM);             // (8, 32)

    // fused fp32->fp16 of all operands (one launch)
    f2h_all<<<(SEQ * DIM + 3 * DIM * DIM) / 1024, 256>>>(X, Wq, Wk, Wv, Xh, Wh);

    // Q, K projections (main stream)
    mma_gemm_h<true, false, true ><<<gQK, blk, SMEM_TOTAL>>>(Xh, Wqh, bq, Qh, DIM, DIM, 1.0f);
    mma_gemm_h<true, false, true ><<<gQK, blk, SMEM_TOTAL>>>(Xh, Wkh, bk, Kh, DIM, DIM, 1.0f);

    // S = (Q @ K^T) / 32
    mma_gemm_h<false, false, false><<<gS, blk, SMEM_TOTAL>>>(Qh, Kh, nullptr, S, DIM, SEQ, 0.03125f);

    // fork: VT projection on side stream, concurrent with softmax
    cudaEventRecord(evS, 0);
    cudaStreamWaitEvent(s1, evS, 0);
    mma_gemm_h<true, true, true ><<<gVT, blk, SMEM_TOTAL, s1>>>(Wvh, Xh, bv, VTh, DIM, SEQ, 1.0f);
    cudaEventRecord(evV, s1);

    softmax4096<<<SEQ, 256>>>(S, P);         // main stream

    // join, then PV
    cudaStreamWaitEvent(0, evV, 0);
    mma_gemm_h<false, false, false><<<gO, blk, SMEM_TOTAL>>>(P, VTh, nullptr, out, SEQ, DIM, 1.0f);
}